// round 8
// baseline (speedup 1.0000x reference)
#include <cuda_runtime.h>
#include <cuda_fp16.h>
#include <math.h>
#include <stdint.h>

#define BATCH 8192
#define DIM   2048
#define NEMB  1000
#define NCLS  1000
#define NPAD  1024

typedef __half f16;

// ---------------- fp32 scratch ----------------
__device__ float d_wn[NEMB * DIM];
__device__ float d_c[NEMB];
__device__ float d_rinv[BATCH];
__device__ float d_S[BATCH * NEMB];
__device__ float d_M[DIM * DIM];
__device__ float d_W[BATCH * DIM];
__device__ float d_Y[NEMB * DIM];
__device__ float d_Z[NEMB * DIM];
__device__ float d_diag[NEMB];
__device__ int   d_bidx[BATCH];
__device__ float d_gap[BATCH];

// ---------------- fp16 hi/lo planes ----------------
__device__ f16 feat_h[BATCH * DIM],  feat_l[BATCH * DIM];
__device__ f16 emb_h[NPAD * DIM],    emb_l[NPAD * DIM];
__device__ f16 wn_h[NPAD * DIM],     wn_l[NPAD * DIM];
__device__ f16 kwt_h[DIM * DIM],     kwt_l[DIM * DIM];
__device__ f16 qwt_h[DIM * DIM],     qwt_l[DIM * DIM];
__device__ f16 vwt_h[DIM * DIM],     vwt_l[DIM * DIM];
__device__ f16 m_h[DIM * DIM],       m_l[DIM * DIM];
__device__ f16 mt_h[DIM * DIM],      mt_l[DIM * DIM];
__device__ f16 fw_h[DIM * 2 * DIM],  fw_l[DIM * 2 * DIM];
__device__ f16 fcw_h[NPAD * DIM],    fcw_l[NPAD * DIM];
__device__ f16 pt_h[DIM * 2 * DIM],  pt_l[DIM * 2 * DIM];
__device__ f16 g_h[BATCH * 2 * DIM];
__device__ f16 h_h[BATCH * DIM];

// ---------------- streams/events ----------------
namespace {
struct Ctx {
    cudaStream_t s1, s2;
    cudaEvent_t eFork, eM, e1, e2;
    Ctx() {
        cudaStreamCreateWithFlags(&s1, cudaStreamNonBlocking);
        cudaStreamCreateWithFlags(&s2, cudaStreamNonBlocking);
        cudaEventCreateWithFlags(&eFork, cudaEventDisableTiming);
        cudaEventCreateWithFlags(&eM,    cudaEventDisableTiming);
        cudaEventCreateWithFlags(&e1,    cudaEventDisableTiming);
        cudaEventCreateWithFlags(&e2,    cudaEventDisableTiming);
    }
};
Ctx g_ctx;
}

// ---------------- helpers ----------------
__device__ __forceinline__ uint32_t smem_to_u32(const void* p) {
    uint32_t a;
    asm("{ .reg .u64 t; cvta.to.shared.u64 t, %1; cvt.u32.u64 %0, t; }" : "=r"(a) : "l"(p));
    return a;
}
__device__ __forceinline__ void split1(float v, f16& h, f16& l) {
    h = __float2half_rn(v);
    l = __float2half_rn(v - __half2float(h));
}
__device__ __forceinline__ void ldsm4(uint32_t* r, uint32_t addr) {
    asm volatile("ldmatrix.sync.aligned.m8n8.x4.shared.b16 {%0,%1,%2,%3}, [%4];"
        : "=r"(r[0]), "=r"(r[1]), "=r"(r[2]), "=r"(r[3]) : "r"(addr));
}
__device__ __forceinline__ void ldsm2(uint32_t* r, uint32_t addr) {
    asm volatile("ldmatrix.sync.aligned.m8n8.x2.shared.b16 {%0,%1}, [%2];"
        : "=r"(r[0]), "=r"(r[1]) : "r"(addr));
}
// main product: f32 accumulate
__device__ __forceinline__ void mma_f32(float* d, const uint32_t* a, const uint32_t* b) {
    asm volatile("mma.sync.aligned.m16n8k16.row.col.f32.f16.f16.f32 "
        "{%0,%1,%2,%3},{%4,%5,%6,%7},{%8,%9},{%0,%1,%2,%3};"
        : "+f"(d[0]), "+f"(d[1]), "+f"(d[2]), "+f"(d[3])
        : "r"(a[0]), "r"(a[1]), "r"(a[2]), "r"(a[3]), "r"(b[0]), "r"(b[1]));
}
// correction products: f16 accumulate (packed f16x2 x2)
__device__ __forceinline__ void mma_f16(uint32_t* d, const uint32_t* a, const uint32_t* b) {
    asm volatile("mma.sync.aligned.m16n8k16.row.col.f16.f16.f16.f16 "
        "{%0,%1},{%2,%3,%4,%5},{%6,%7},{%0,%1};"
        : "+r"(d[0]), "+r"(d[1])
        : "r"(a[0]), "r"(a[1]), "r"(a[2]), "r"(a[3]), "r"(b[0]), "r"(b[1]));
}
__device__ __forceinline__ void cpa16(uint32_t dst, const void* src) {
    asm volatile("cp.async.cg.shared.global [%0], [%1], 16;" :: "r"(dst), "l"(src));
}
#define CP_COMMIT() asm volatile("cp.async.commit_group;" ::: "memory")
#define CP_WAIT(n)  asm volatile("cp.async.wait_group %0;" :: "n"(n) : "memory")

// ================= tensor-core GEMM (pre-split fp16, NT) =================
// NPROD=1: Ah*Bh only. NPROD=2: + Ah*Bl (f16 acc). NPROD=3: + Al*Bh (f16 acc).
// EPI bits: 1=bias, 2=relu, 4=write f32, 8=write f16 planes, 16=hi plane only
#define BM 128
#define BN 128
#define STAGE_BYTES 32768
#define SMEM_BYTES  (2 * STAGE_BYTES)

template<int EPI, int NPROD>
__global__ __launch_bounds__(256, (NPROD == 1 ? 2 : 1))
void tc_gemm(const f16* __restrict__ Ah, const f16* __restrict__ Al,
             const f16* __restrict__ Bh, const f16* __restrict__ Bl,
             const float* __restrict__ bias,
             float* __restrict__ Cf, f16* __restrict__ Ch, f16* __restrict__ Cl,
             int M, int N, int K, int lda, int ldb, int ldc)
{
    extern __shared__ char smem[];
    const int tid  = threadIdx.x;
    const int lane = tid & 31;
    const int wid  = tid >> 5;
    const int wm   = (wid >> 2) << 6;
    const int wn   = (wid & 3) << 5;
    const int bm   = blockIdx.y * BM;
    const int bn   = blockIdx.x * BN;
    const uint32_t sb = smem_to_u32(smem);

    float acc[4][4][4];
    uint32_t accc[4][4][2];
    #pragma unroll
    for (int i = 0; i < 4; i++)
        #pragma unroll
        for (int j = 0; j < 4; j++) {
            #pragma unroll
            for (int k = 0; k < 4; k++) acc[i][j][k] = 0.f;
            accc[i][j][0] = 0u; accc[i][j][1] = 0u;
        }

    auto copy = [&](int s, int k0) {
        uint32_t base = sb + s * STAGE_BYTES;
        #pragma unroll
        for (int i = 0; i < 4; i++) {
            int id = (i << 8) + tid;
            int row = id >> 3, rem = id & 7, pl = rem >> 2, u = rem & 3;
            if (NPROD == 3 || pl == 0) {
                const f16* src = (pl ? Al : Ah) + (size_t)(bm + row) * lda + k0 + (u << 3);
                uint32_t dst = base + row * 128 + ((((u ^ (row & 7))) ^ (pl << 2)) << 4);
                cpa16(dst, src);
            }
        }
        #pragma unroll
        for (int i = 0; i < 4; i++) {
            int id = (i << 8) + tid;
            int row = id >> 3, rem = id & 7, pl = rem >> 2, u = rem & 3;
            if (NPROD >= 2 || pl == 0) {
                const f16* src = (pl ? Bl : Bh) + (size_t)(bn + row) * ldb + k0 + (u << 3);
                uint32_t dst = base + 16384 + row * 128 + ((((u ^ (row & 7))) ^ (pl << 2)) << 4);
                cpa16(dst, src);
            }
        }
    };

    copy(0, 0);
    CP_COMMIT();

    const int nc = K >> 5;
    for (int c = 0; c < nc; c++) {
        int s = c & 1;
        if (c + 1 < nc) {
            copy(s ^ 1, (c + 1) << 5);
            CP_COMMIT();
            CP_WAIT(1);
        } else {
            CP_WAIT(0);
        }
        __syncthreads();

        uint32_t a_s = sb + s * STAGE_BYTES;
        uint32_t b_s = a_s + 16384;
        #pragma unroll
        for (int h = 0; h < 2; h++) {
            uint32_t bhf[4][2], blf[4][2];
            #pragma unroll
            for (int nt = 0; nt < 4; nt++) {
                int r = wn + (nt << 3) + (lane & 7);
                int lu = (h << 1) + ((lane >> 3) & 1);
                uint32_t ad = b_s + r * 128 + ((uint32_t)(lu ^ (r & 7)) << 4);
                ldsm2(bhf[nt], ad);
                if (NPROD >= 2) ldsm2(blf[nt], ad ^ 64u);
            }
            #pragma unroll
            for (int mt = 0; mt < 4; mt++) {
                int g = lane >> 3;
                int r = wm + (mt << 4) + ((g & 1) << 3) + (lane & 7);
                int lu = (h << 1) + (g >> 1);
                uint32_t ad = a_s + r * 128 + ((uint32_t)(lu ^ (r & 7)) << 4);
                uint32_t af[4];
                ldsm4(af, ad);                       // A hi
                #pragma unroll
                for (int nt = 0; nt < 4; nt++) mma_f32(acc[mt][nt], af, bhf[nt]);
                if (NPROD >= 2) {
                    #pragma unroll
                    for (int nt = 0; nt < 4; nt++) mma_f16(accc[mt][nt], af, blf[nt]);
                }
                if (NPROD == 3) {
                    ldsm4(af, ad ^ 64u);             // A lo
                    #pragma unroll
                    for (int nt = 0; nt < 4; nt++) mma_f16(accc[mt][nt], af, bhf[nt]);
                }
            }
        }
        __syncthreads();
    }

    // epilogue
    #pragma unroll
    for (int mt = 0; mt < 4; mt++) {
        int r0 = bm + wm + (mt << 4) + (lane >> 2);
        #pragma unroll
        for (int half = 0; half < 2; half++) {
            int rr = r0 + half * 8;
            if (rr >= M) continue;
            #pragma unroll
            for (int nt = 0; nt < 4; nt++) {
                int cn = bn + wn + (nt << 3) + ((lane & 3) << 1);
                float v0 = acc[mt][nt][half * 2 + 0];
                float v1 = acc[mt][nt][half * 2 + 1];
                if (NPROD >= 2) {
                    __half2 hc = *reinterpret_cast<__half2*>(&accc[mt][nt][half]);
                    v0 += __half2float(__low2half(hc));
                    v1 += __half2float(__high2half(hc));
                }
                if (EPI & 1) {
                    if (cn < N)     v0 += bias[cn];
                    if (cn + 1 < N) v1 += bias[cn + 1];
                }
                if (EPI & 2) { v0 = fmaxf(v0, 0.f); v1 = fmaxf(v1, 0.f); }
                if (EPI & 4) {
                    if (cn < N)     Cf[(size_t)rr * ldc + cn] = v0;
                    if (cn + 1 < N) Cf[(size_t)rr * ldc + cn + 1] = v1;
                }
                if (EPI & 8) {
                    if (cn + 1 < N) {
                        f16 h0, l0, h1, l1;
                        split1(v0, h0, l0);
                        split1(v1, h1, l1);
                        uint32_t hp = (uint32_t)__half_as_ushort(h0) | ((uint32_t)__half_as_ushort(h1) << 16);
                        *(uint32_t*)(Ch + (size_t)rr * ldc + cn) = hp;
                        if (!(EPI & 16)) {
                            uint32_t lp = (uint32_t)__half_as_ushort(l0) | ((uint32_t)__half_as_ushort(l1) << 16);
                            *(uint32_t*)(Cl + (size_t)rr * ldc + cn) = lp;
                        }
                    } else if (cn < N) {
                        f16 h0, l0;
                        split1(v0, h0, l0);
                        Ch[(size_t)rr * ldc + cn] = h0;
                        if (!(EPI & 16)) Cl[(size_t)rr * ldc + cn] = l0;
                    }
                }
            }
        }
    }
}

// ================= small kernels =================
__device__ __forceinline__ float warpReduceSum(float v) {
    #pragma unroll
    for (int o = 16; o > 0; o >>= 1) v += __shfl_down_sync(0xffffffffu, v, o);
    return v;
}
__device__ __forceinline__ float blockReduceSum(float v, float* smem) {
    __syncthreads();
    int lane = threadIdx.x & 31, wid = threadIdx.x >> 5;
    v = warpReduceSum(v);
    if (lane == 0) smem[wid] = v;
    __syncthreads();
    int nw = blockDim.x >> 5;
    float t = (threadIdx.x < nw) ? smem[threadIdx.x] : 0.0f;
    if (wid == 0) { t = warpReduceSum(t); if (lane == 0) smem[0] = t; }
    __syncthreads();
    return smem[0];
}

__global__ __launch_bounds__(256) void transpose_bf_kernel(
    const float* __restrict__ in, f16* __restrict__ oh, f16* __restrict__ ol)
{
    __shared__ float t[32][33];
    int bx = blockIdx.x * 32, by = blockIdx.y * 32;
    #pragma unroll
    for (int j = threadIdx.y; j < 32; j += 8)
        t[j][threadIdx.x] = in[(size_t)(by + j) * DIM + bx + threadIdx.x];
    __syncthreads();
    #pragma unroll
    for (int j = threadIdx.y; j < 32; j += 8) {
        float v = t[threadIdx.x][j];
        f16 h, l;
        split1(v, h, l);
        size_t o = (size_t)(bx + j) * DIM + by + threadIdx.x;
        oh[o] = h; ol[o] = l;
    }
}

__global__ __launch_bounds__(256) void split_pad_kernel(
    const float* __restrict__ src, f16* __restrict__ dh, f16* __restrict__ dl,
    int valid, int total)
{
    int i = (blockIdx.x * 256 + threadIdx.x) * 4;
    if (i >= total) return;
    float4 v;
    if (i + 3 < valid) v = *(const float4*)(src + i);
    else {
        v.x = (i + 0 < valid) ? src[i + 0] : 0.f;
        v.y = (i + 1 < valid) ? src[i + 1] : 0.f;
        v.z = (i + 2 < valid) ? src[i + 2] : 0.f;
        v.w = (i + 3 < valid) ? src[i + 3] : 0.f;
    }
    f16 h0, l0, h1, l1, h2, l2, h3, l3;
    split1(v.x, h0, l0); split1(v.y, h1, l1);
    split1(v.z, h2, l2); split1(v.w, h3, l3);
    uint2 hp = make_uint2(
        (uint32_t)__half_as_ushort(h0) | ((uint32_t)__half_as_ushort(h1) << 16),
        (uint32_t)__half_as_ushort(h2) | ((uint32_t)__half_as_ushort(h3) << 16));
    uint2 lp = make_uint2(
        (uint32_t)__half_as_ushort(l0) | ((uint32_t)__half_as_ushort(l1) << 16),
        (uint32_t)__half_as_ushort(l2) | ((uint32_t)__half_as_ushort(l3) << 16));
    *(uint2*)(dh + i) = hp;
    *(uint2*)(dl + i) = lp;
}

__global__ __launch_bounds__(256) void embed_norm_kernel(const float* __restrict__ emb) {
    int n = blockIdx.x, tid = threadIdx.x;
    if (n >= NEMB) {
        f16 z = __float2half_rn(0.f);
        for (int j = tid; j < DIM; j += 256) {
            wn_h[(size_t)n * DIM + j] = z;
            wn_l[(size_t)n * DIM + j] = z;
        }
        return;
    }
    const float* row = emb + (size_t)n * DIM;
    float s = 0.0f;
    for (int j = tid; j < DIM; j += 256) { float v = row[j]; s = fmaf(v, v, s); }
    __shared__ float red[32];
    s = blockReduceSum(s, red);
    float inv = 1.0f / fmaxf(sqrtf(s), 1e-12f);
    float c = 0.0f;
    for (int j = tid; j < DIM; j += 256) {
        float v = row[j] * inv;
        d_wn[(size_t)n * DIM + j] = v;
        f16 h, l;
        split1(v, h, l);
        wn_h[(size_t)n * DIM + j] = h;
        wn_l[(size_t)n * DIM + j] = l;
        c = fmaf(v, v, c);
    }
    c = blockReduceSum(c, red);
    if (tid == 0) d_c[n] = c;
}

__global__ __launch_bounds__(256) void feat_norm_kernel(const float* __restrict__ feat) {
    int b = blockIdx.x, tid = threadIdx.x;
    const float* row = feat + (size_t)b * DIM;
    float s = 0.0f;
    for (int j = tid; j < DIM; j += 256) { float v = row[j]; s = fmaf(v, v, s); }
    __shared__ float red[32];
    s = blockReduceSum(s, red);
    if (tid == 0) d_rinv[b] = 1.0f / fmaxf(sqrtf(s), 1e-12f);
}

__global__ __launch_bounds__(256) void argmin_kernel() {
    int b = blockIdx.x, tid = threadIdx.x;
    float r = d_rinv[b];
    float best = INFINITY, sec = INFINITY;
    int bi = 0x7fffffff;
    for (int n = tid; n < NEMB; n += 256) {
        float v = d_c[n] - 2.0f * r * d_S[(size_t)b * NEMB + n];
        if (v < best) { sec = best; best = v; bi = n; }
        else if (v < sec) sec = v;
    }
    __shared__ float rb[256], rs[256];
    __shared__ int ri[256];
    rb[tid] = best; rs[tid] = sec; ri[tid] = bi;
    __syncthreads();
    #pragma unroll
    for (int off = 128; off > 0; off >>= 1) {
        if (tid < off) {
            float b1 = rb[tid], s1 = rs[tid], b2 = rb[tid + off], s2 = rs[tid + off];
            int i1 = ri[tid], i2 = ri[tid + off];
            float nb, ns; int ni;
            if (b2 < b1)      { nb = b2; ni = i2; ns = fminf(b1, s2); }
            else if (b1 < b2) { nb = b1; ni = i1; ns = fminf(b2, s1); }
            else              { nb = b1; ni = min(i1, i2); ns = b2; }
            rb[tid] = nb; rs[tid] = ns; ri[tid] = ni;
        }
        __syncthreads();
    }
    if (tid == 0) { d_bidx[b] = ri[0]; d_gap[b] = rs[0] - rb[0]; }
}

__global__ __launch_bounds__(256) void refine_gather_kernel(
    const float* __restrict__ emb, const float* __restrict__ feat,
    float* __restrict__ outq, float* __restrict__ outi)
{
    int b = blockIdx.x, tid = threadIdx.x;
    int idx = d_bidx[b];
    if (d_gap[b] < 1e-3f) {
        __shared__ float sf[DIM];
        const float* f = feat + (size_t)b * DIM;
        for (int j = tid; j < DIM; j += 256) sf[j] = f[j];
        __syncthreads();
        float r = d_rinv[b];
        int wid = tid >> 5, lane = tid & 31;
        float best = INFINITY; int bi = 0x7fffffff;
        for (int n = wid; n < NEMB; n += 8) {
            const float* w = d_wn + (size_t)n * DIM;
            float s = 0.0f;
            for (int j = lane; j < DIM; j += 32) s = fmaf(sf[j], w[j], s);
            s = warpReduceSum(s);
            s = __shfl_sync(0xffffffffu, s, 0);
            float v = d_c[n] - 2.0f * r * s;
            if (v < best) { best = v; bi = n; }
        }
        __shared__ float wb[8]; __shared__ int wi[8];
        if (lane == 0) { wb[wid] = best; wi[wid] = bi; }
        __syncthreads();
        if (tid == 0) {
            float bb = wb[0]; int ii = wi[0];
            for (int w = 1; w < 8; w++)
                if (wb[w] < bb || (wb[w] == bb && wi[w] < ii)) { bb = wb[w]; ii = wi[w]; }
            wi[0] = ii;
        }
        __syncthreads();
        idx = wi[0];
        if (tid == 0) d_bidx[b] = idx;
    }
    const float* src = emb + (size_t)idx * DIM;
    float* dst = outq + (size_t)b * DIM;
    for (int j = tid; j < DIM; j += 256) dst[j] = src[j];
    if (tid == 0) outi[b] = (float)idx;
}

__global__ __launch_bounds__(256) void diag_kernel(const float* __restrict__ emb) {
    int n = blockIdx.x, tid = threadIdx.x;
    const float* y = d_Y + (size_t)n * DIM;
    const float* e = emb + (size_t)n * DIM;
    float s = 0.0f;
    for (int j = tid; j < DIM; j += 256) s = fmaf(y[j], e[j], s);
    __shared__ float red[32];
    s = blockReduceSum(s, red);
    if (tid == 0) d_diag[n] = s;
}

__global__ __launch_bounds__(256) void attn_mix2_kernel(
    const float* __restrict__ feat, const float* __restrict__ outq)
{
    int b = blockIdx.x, tid = threadIdx.x;
    int idx = d_bidx[b];
    const float* t1 = feat + (size_t)b * DIM;
    const float* t0 = outq + (size_t)b * DIM;
    const float* yr = d_Y + (size_t)idx * DIM;
    const float* zr = d_Z + (size_t)idx * DIM;
    const float* wr = d_W + (size_t)b * DIM;
    float s01 = 0, s10 = 0, s11 = 0;
    for (int j = tid; j < DIM; j += 256) {
        float f = t1[j];
        s01 = fmaf(yr[j], f, s01);
        s10 = fmaf(zr[j], f, s10);
        s11 = fmaf(wr[j], f, s11);
    }
    __shared__ float red[32];
    s01 = blockReduceSum(s01, red);
    s10 = blockReduceSum(s10, red);
    s11 = blockReduceSum(s11, red);
    float s00 = d_diag[idx];
    float m0 = fmaxf(s00, s10);
    float e00 = expf(s00 - m0), e10 = expf(s10 - m0);
    float iv0 = 1.0f / (e00 + e10);
    float a00 = e00 * iv0, a10 = e10 * iv0;
    float m1 = fmaxf(s01, s11);
    float e01 = expf(s01 - m1), e11 = expf(s11 - m1);
    float iv1 = 1.0f / (e01 + e11);
    float a01 = e01 * iv1, a11 = e11 * iv1;
    size_t go = (size_t)b * 2 * DIM;
    for (int j = tid; j < DIM; j += 256) {
        float v0 = t0[j], v1 = t1[j];
        g_h[go + j]       = __float2half_rn(fmaf(a00, v0, a10 * v1));
        g_h[go + DIM + j] = __float2half_rn(fmaf(a01, v0, a11 * v1));
    }
}

// ================= launch =================
extern "C" void kernel_launch(void* const* d_in, const int* in_sizes, int n_in,
                              void* d_out, int out_size)
{
    const float* feat = (const float*)d_in[0];
    const float* emb  = (const float*)d_in[1];
    const float* Kw   = (const float*)d_in[2];
    const float* Qw   = (const float*)d_in[3];
    const float* Vw   = (const float*)d_in[4];
    const float* fw   = (const float*)d_in[5];
    const float* fb   = (const float*)d_in[6];
    const float* fcw  = (const float*)d_in[7];
    const float* fcb  = (const float*)d_in[8];

    float* out  = (float*)d_out;
    float* outq = out;
    float* outp = out + (size_t)BATCH * DIM;
    float* outi = outp + (size_t)BATCH * NCLS;

    float *S, *Mm, *W, *Y, *Z;
    f16 *p_feath, *p_featl, *p_embh, *p_embl, *p_wnh, *p_wnl;
    f16 *p_kwth, *p_kwtl, *p_qwth, *p_qwtl, *p_vwth, *p_vwtl;
    f16 *p_mh, *p_ml, *p_mth, *p_mtl, *p_fwh, *p_fwl, *p_fcwh, *p_fcwl;
    f16 *p_pth, *p_ptl, *p_gh, *p_hh;
    cudaGetSymbolAddress((void**)&S,   d_S);
    cudaGetSymbolAddress((void**)&Mm,  d_M);
    cudaGetSymbolAddress((void**)&W,   d_W);
    cudaGetSymbolAddress((void**)&Y,   d_Y);
    cudaGetSymbolAddress((void**)&Z,   d_Z);
    cudaGetSymbolAddress((void**)&p_feath, feat_h); cudaGetSymbolAddress((void**)&p_featl, feat_l);
    cudaGetSymbolAddress((void**)&p_embh,  emb_h);  cudaGetSymbolAddress((void**)&p_embl,  emb_l);
    cudaGetSymbolAddress((void**)&p_wnh,   wn_h);   cudaGetSymbolAddress((void**)&p_wnl,   wn_l);
    cudaGetSymbolAddress((void**)&p_kwth,  kwt_h);  cudaGetSymbolAddress((void**)&p_kwtl,  kwt_l);
    cudaGetSymbolAddress((void**)&p_qwth,  qwt_h);  cudaGetSymbolAddress((void**)&p_qwtl,  qwt_l);
    cudaGetSymbolAddress((void**)&p_vwth,  vwt_h);  cudaGetSymbolAddress((void**)&p_vwtl,  vwt_l);
    cudaGetSymbolAddress((void**)&p_mh,    m_h);    cudaGetSymbolAddress((void**)&p_ml,    m_l);
    cudaGetSymbolAddress((void**)&p_mth,   mt_h);   cudaGetSymbolAddress((void**)&p_mtl,   mt_l);
    cudaGetSymbolAddress((void**)&p_fwh,   fw_h);   cudaGetSymbolAddress((void**)&p_fwl,   fw_l);
    cudaGetSymbolAddress((void**)&p_fcwh,  fcw_h);  cudaGetSymbolAddress((void**)&p_fcwl,  fcw_l);
    cudaGetSymbolAddress((void**)&p_pth,   pt_h);   cudaGetSymbolAddress((void**)&p_ptl,   pt_l);
    cudaGetSymbolAddress((void**)&p_gh,    g_h);
    cudaGetSymbolAddress((void**)&p_hh,    h_h);

    cudaFuncSetAttribute((const void*)tc_gemm<4, 1>,  cudaFuncAttributeMaxDynamicSharedMemorySize, SMEM_BYTES);
    cudaFuncSetAttribute((const void*)tc_gemm<4, 3>,  cudaFuncAttributeMaxDynamicSharedMemorySize, SMEM_BYTES);
    cudaFuncSetAttribute((const void*)tc_gemm<12, 3>, cudaFuncAttributeMaxDynamicSharedMemorySize, SMEM_BYTES);
    cudaFuncSetAttribute((const void*)tc_gemm<8, 2>,  cudaFuncAttributeMaxDynamicSharedMemorySize, SMEM_BYTES);
    cudaFuncSetAttribute((const void*)tc_gemm<27, 2>, cudaFuncAttributeMaxDynamicSharedMemorySize, SMEM_BYTES);
    cudaFuncSetAttribute((const void*)tc_gemm<5, 2>,  cudaFuncAttributeMaxDynamicSharedMemorySize, SMEM_BYTES);

    cudaStream_t s1 = g_ctx.s1, s2 = g_ctx.s2;
    dim3 tb(32, 8);
    dim3 tg(DIM / 32, DIM / 32);

    // ---- default stream prefix ----
    split_pad_kernel<<<(BATCH * DIM / 4 + 255) / 256, 256>>>(feat, p_feath, p_featl, BATCH * DIM, BATCH * DIM);
    embed_norm_kernel<<<NPAD, 256>>>(emb);
    split_pad_kernel<<<(NPAD * DIM / 4 + 255) / 256, 256>>>(emb, p_embh, p_embl, NEMB * DIM, NPAD * DIM);
    cudaEventRecord(g_ctx.eFork, 0);

    // ---- s1: M chain -> Y -> diag ----
    cudaStreamWaitEvent(s1, g_ctx.eFork, 0);
    transpose_bf_kernel<<<tg, tb, 0, s1>>>(Kw, p_kwth, p_kwtl);
    transpose_bf_kernel<<<tg, tb, 0, s1>>>(Qw, p_qwth, p_qwtl);
    tc_gemm<12, 3><<<dim3(DIM / BN, DIM / BM), 256, SMEM_BYTES, s1>>>(
        p_kwth, p_kwtl, p_qwth, p_qwtl, nullptr, Mm, p_mh, p_ml,
        DIM, DIM, DIM, DIM, DIM, DIM);
    cudaEventRecord(g_ctx.eM, s1);
    transpose_bf_kernel<<<tg, tb, 0, s1>>>(Mm, p_mth, p_mtl);
    tc_gemm<4, 3><<<dim3(DIM / BN, NPAD / BM), 256, SMEM_BYTES, s1>>>(
        p_embh, p_embl, p_mth, p_mtl, nullptr, Y, nullptr, nullptr,
        NEMB, DIM, DIM, DIM, DIM, DIM);
    diag_kernel<<<NEMB, 256, 0, s1>>>(emb);
    cudaEventRecord(g_ctx.e1, s1);

    // ---- s2: Vw/fw/fcw prep -> Z -> PT ----
    cudaStreamWaitEvent(s2, g_ctx.eFork, 0);
    transpose_bf_kernel<<<tg, tb, 0, s2>>>(Vw, p_vwth, p_vwtl);
    split_pad_kernel<<<(DIM * 2 * DIM / 4 + 255) / 256, 256, 0, s2>>>(fw, p_fwh, p_fwl, DIM * 2 * DIM, DIM * 2 * DIM);
    split_pad_kernel<<<(NPAD * DIM / 4 + 255) / 256, 256, 0, s2>>>(fcw, p_fcwh, p_fcwl, NCLS * DIM, NPAD * DIM);
    cudaStreamWaitEvent(s2, g_ctx.eM, 0);
    tc_gemm<4, 3><<<dim3(DIM / BN, NPAD / BM), 256, SMEM_BYTES, s2>>>(
        p_embh, p_embl, p_mh, p_ml, nullptr, Z, nullptr, nullptr,
        NEMB, DIM, DIM, DIM, DIM, DIM);
    tc_gemm<8, 2><<<dim3(DIM / BN, DIM / BM), 256, SMEM_BYTES, s2>>>(
        p_fwh,       nullptr, p_vwth, p_vwtl, nullptr, nullptr, p_pth,       p_ptl,
        DIM, DIM, DIM, 2 * DIM, DIM, 2 * DIM);
    tc_gemm<8, 2><<<dim3(DIM / BN, DIM / BM), 256, SMEM_BYTES, s2>>>(
        p_fwh + DIM, nullptr, p_vwth, p_vwtl, nullptr, nullptr, p_pth + DIM, p_ptl + DIM,
        DIM, DIM, DIM, 2 * DIM, DIM, 2 * DIM);
    cudaEventRecord(g_ctx.e2, s2);

    // ---- default stream: S chain (1-product) -> W ----
    feat_norm_kernel<<<BATCH, 256>>>(feat);
    tc_gemm<4, 1><<<dim3(NPAD / BN, BATCH / BM), 256, SMEM_BYTES>>>(
        p_feath, nullptr, p_wnh, nullptr, nullptr, S, nullptr, nullptr,
        BATCH, NEMB, DIM, DIM, DIM, NEMB);
    argmin_kernel<<<BATCH, 256>>>();
    refine_gather_kernel<<<BATCH, 256>>>(emb, feat, outq, outi);
    cudaStreamWaitEvent(0, g_ctx.eM, 0);
    tc_gemm<4, 3><<<dim3(DIM / BN, BATCH / BM), 256, SMEM_BYTES>>>(
        p_feath, p_featl, p_mh, p_ml, nullptr, W, nullptr, nullptr,
        BATCH, DIM, DIM, DIM, DIM, DIM);

    // ---- join, then tail chain ----
    cudaStreamWaitEvent(0, g_ctx.e1, 0);
    cudaStreamWaitEvent(0, g_ctx.e2, 0);
    attn_mix2_kernel<<<BATCH, 256>>>(feat, outq);
    tc_gemm<27, 2><<<dim3(DIM / BN, BATCH / BM), 256, SMEM_BYTES>>>(
        p_gh, nullptr, p_pth, p_ptl, fb, nullptr, p_hh, nullptr,
        BATCH, DIM, 2 * DIM, 2 * DIM, 2 * DIM, DIM);
    tc_gemm<5, 2><<<dim3(NPAD / BN, BATCH / BM), 256, SMEM_BYTES>>>(
        p_hh, nullptr, p_fcwh, p_fcwl, fcb, outp, nullptr, nullptr,
        BATCH, NCLS, DIM, DIM, DIM, NCLS);
}

// round 9
// speedup vs baseline: 1.1239x; 1.1239x over previous
#include <cuda_runtime.h>
#include <cuda_fp16.h>
#include <math.h>
#include <stdint.h>

#define BATCH 8192
#define DIM   2048
#define NEMB  1000
#define NCLS  1000
#define NPAD  1024

typedef __half f16;

// ---------------- fp32 scratch ----------------
__device__ float d_wn[NEMB * DIM];
__device__ float d_c[NEMB];
__device__ float d_rinv[BATCH];
__device__ float d_S[BATCH * NEMB];
__device__ float d_M[DIM * DIM];
__device__ float d_W[BATCH * DIM];
__device__ float d_Y[NEMB * DIM];
__device__ float d_Z[NEMB * DIM];
__device__ float d_diag[NEMB];
__device__ int   d_bidx[BATCH];
__device__ float d_gap[BATCH];

// ---------------- fp16 hi/lo planes ----------------
__device__ f16 feat_h[BATCH * DIM],  feat_l[BATCH * DIM];
__device__ f16 emb_h[NPAD * DIM],    emb_l[NPAD * DIM];
__device__ f16 wn_h[NPAD * DIM],     wn_l[NPAD * DIM];
__device__ f16 kwt_h[DIM * DIM],     kwt_l[DIM * DIM];
__device__ f16 qwt_h[DIM * DIM],     qwt_l[DIM * DIM];
__device__ f16 vwt_h[DIM * DIM],     vwt_l[DIM * DIM];
__device__ f16 m_h[DIM * DIM],       m_l[DIM * DIM];
__device__ f16 mt_h[DIM * DIM],      mt_l[DIM * DIM];
__device__ f16 fw_h[DIM * 2 * DIM],  fw_l[DIM * 2 * DIM];
__device__ f16 fcw_h[NPAD * DIM],    fcw_l[NPAD * DIM];
__device__ f16 pt_h[DIM * 2 * DIM],  pt_l[DIM * 2 * DIM];
__device__ f16 g_h[BATCH * 2 * DIM];
__device__ f16 h_h[BATCH * DIM];

// ---------------- streams/events ----------------
namespace {
struct Ctx {
    cudaStream_t s1, s2;
    cudaEvent_t eFork, eM, e1, e2;
    Ctx() {
        cudaStreamCreateWithFlags(&s1, cudaStreamNonBlocking);
        cudaStreamCreateWithFlags(&s2, cudaStreamNonBlocking);
        cudaEventCreateWithFlags(&eFork, cudaEventDisableTiming);
        cudaEventCreateWithFlags(&eM,    cudaEventDisableTiming);
        cudaEventCreateWithFlags(&e1,    cudaEventDisableTiming);
        cudaEventCreateWithFlags(&e2,    cudaEventDisableTiming);
    }
};
Ctx g_ctx;
}

// ---------------- helpers ----------------
__device__ __forceinline__ uint32_t smem_to_u32(const void* p) {
    uint32_t a;
    asm("{ .reg .u64 t; cvta.to.shared.u64 t, %1; cvt.u32.u64 %0, t; }" : "=r"(a) : "l"(p));
    return a;
}
__device__ __forceinline__ void split1(float v, f16& h, f16& l) {
    h = __float2half_rn(v);
    l = __float2half_rn(v - __half2float(h));
}
__device__ __forceinline__ void ldsm4(uint32_t* r, uint32_t addr) {
    asm volatile("ldmatrix.sync.aligned.m8n8.x4.shared.b16 {%0,%1,%2,%3}, [%4];"
        : "=r"(r[0]), "=r"(r[1]), "=r"(r[2]), "=r"(r[3]) : "r"(addr));
}
__device__ __forceinline__ void ldsm2(uint32_t* r, uint32_t addr) {
    asm volatile("ldmatrix.sync.aligned.m8n8.x2.shared.b16 {%0,%1}, [%2];"
        : "=r"(r[0]), "=r"(r[1]) : "r"(addr));
}
__device__ __forceinline__ void mma16816(float* d, const uint32_t* a, const uint32_t* b) {
    asm volatile("mma.sync.aligned.m16n8k16.row.col.f32.f16.f16.f32 "
        "{%0,%1,%2,%3},{%4,%5,%6,%7},{%8,%9},{%0,%1,%2,%3};"
        : "+f"(d[0]), "+f"(d[1]), "+f"(d[2]), "+f"(d[3])
        : "r"(a[0]), "r"(a[1]), "r"(a[2]), "r"(a[3]), "r"(b[0]), "r"(b[1]));
}
__device__ __forceinline__ void cpa16(uint32_t dst, const void* src) {
    asm volatile("cp.async.cg.shared.global [%0], [%1], 16;" :: "r"(dst), "l"(src));
}
#define CP_COMMIT() asm volatile("cp.async.commit_group;" ::: "memory")
#define CP_WAIT(n)  asm volatile("cp.async.wait_group %0;" :: "n"(n) : "memory")

// ================= tensor-core GEMM (pre-split fp16, NT, all f32 acc) =================
// NPROD=1: Ah*Bh. NPROD=2: + Ah*Bl. NPROD=3: + Al*Bh.
// EPI bits: 1=bias, 2=relu, 4=write f32, 8=write f16 planes, 16=hi plane only
#define BM 128
#define BN 128
#define STAGE_BYTES 32768
#define SMEM_BYTES  (2 * STAGE_BYTES)

template<int EPI, int NPROD>
__global__ __launch_bounds__(256, 2)
void tc_gemm(const f16* __restrict__ Ah, const f16* __restrict__ Al,
             const f16* __restrict__ Bh, const f16* __restrict__ Bl,
             const float* __restrict__ bias,
             float* __restrict__ Cf, f16* __restrict__ Ch, f16* __restrict__ Cl,
             int M, int N, int K, int lda, int ldb, int ldc)
{
    extern __shared__ char smem[];
    const int tid  = threadIdx.x;
    const int lane = tid & 31;
    const int wid  = tid >> 5;
    const int wm   = (wid >> 2) << 6;
    const int wn   = (wid & 3) << 5;
    const int bm   = blockIdx.y * BM;
    const int bn   = blockIdx.x * BN;
    const uint32_t sb = smem_to_u32(smem);

    float acc[4][4][4];
    #pragma unroll
    for (int i = 0; i < 4; i++)
        #pragma unroll
        for (int j = 0; j < 4; j++)
            #pragma unroll
            for (int k = 0; k < 4; k++) acc[i][j][k] = 0.f;

    auto copy = [&](int s, int k0) {
        uint32_t base = sb + s * STAGE_BYTES;
        #pragma unroll
        for (int i = 0; i < 4; i++) {
            int id = (i << 8) + tid;
            int row = id >> 3, rem = id & 7, pl = rem >> 2, u = rem & 3;
            if (NPROD == 3 || pl == 0) {
                const f16* src = (pl ? Al : Ah) + (size_t)(bm + row) * lda + k0 + (u << 3);
                uint32_t dst = base + row * 128 + ((((u ^ (row & 7))) ^ (pl << 2)) << 4);
                cpa16(dst, src);
            }
        }
        #pragma unroll
        for (int i = 0; i < 4; i++) {
            int id = (i << 8) + tid;
            int row = id >> 3, rem = id & 7, pl = rem >> 2, u = rem & 3;
            if (NPROD >= 2 || pl == 0) {
                const f16* src = (pl ? Bl : Bh) + (size_t)(bn + row) * ldb + k0 + (u << 3);
                uint32_t dst = base + 16384 + row * 128 + ((((u ^ (row & 7))) ^ (pl << 2)) << 4);
                cpa16(dst, src);
            }
        }
    };

    copy(0, 0);
    CP_COMMIT();

    const int nc = K >> 5;
    for (int c = 0; c < nc; c++) {
        int s = c & 1;
        if (c + 1 < nc) {
            copy(s ^ 1, (c + 1) << 5);
            CP_COMMIT();
            CP_WAIT(1);
        } else {
            CP_WAIT(0);
        }
        __syncthreads();

        uint32_t a_s = sb + s * STAGE_BYTES;
        uint32_t b_s = a_s + 16384;
        #pragma unroll
        for (int h = 0; h < 2; h++) {
            uint32_t bhf[4][2], blf[4][2];
            #pragma unroll
            for (int nt = 0; nt < 4; nt++) {
                int r = wn + (nt << 3) + (lane & 7);
                int lu = (h << 1) + ((lane >> 3) & 1);
                uint32_t ad = b_s + r * 128 + ((uint32_t)(lu ^ (r & 7)) << 4);
                ldsm2(bhf[nt], ad);
                if (NPROD >= 2) ldsm2(blf[nt], ad ^ 64u);
            }
            #pragma unroll
            for (int mt = 0; mt < 4; mt++) {
                int g = lane >> 3;
                int r = wm + (mt << 4) + ((g & 1) << 3) + (lane & 7);
                int lu = (h << 1) + (g >> 1);
                uint32_t ad = a_s + r * 128 + ((uint32_t)(lu ^ (r & 7)) << 4);
                uint32_t af[4];
                ldsm4(af, ad);                       // A hi
                #pragma unroll
                for (int nt = 0; nt < 4; nt++) mma16816(acc[mt][nt], af, bhf[nt]);
                if (NPROD >= 2) {
                    #pragma unroll
                    for (int nt = 0; nt < 4; nt++) mma16816(acc[mt][nt], af, blf[nt]);
                }
                if (NPROD == 3) {
                    ldsm4(af, ad ^ 64u);             // A lo
                    #pragma unroll
                    for (int nt = 0; nt < 4; nt++) mma16816(acc[mt][nt], af, bhf[nt]);
                }
            }
        }
        __syncthreads();
    }

    // epilogue
    #pragma unroll
    for (int mt = 0; mt < 4; mt++) {
        int r0 = bm + wm + (mt << 4) + (lane >> 2);
        #pragma unroll
        for (int half = 0; half < 2; half++) {
            int rr = r0 + half * 8;
            if (rr >= M) continue;
            #pragma unroll
            for (int nt = 0; nt < 4; nt++) {
                int cn = bn + wn + (nt << 3) + ((lane & 3) << 1);
                float v0 = acc[mt][nt][half * 2 + 0];
                float v1 = acc[mt][nt][half * 2 + 1];
                if (EPI & 1) {
                    if (cn < N)     v0 += bias[cn];
                    if (cn + 1 < N) v1 += bias[cn + 1];
                }
                if (EPI & 2) { v0 = fmaxf(v0, 0.f); v1 = fmaxf(v1, 0.f); }
                if (EPI & 4) {
                    if (cn < N)     Cf[(size_t)rr * ldc + cn] = v0;
                    if (cn + 1 < N) Cf[(size_t)rr * ldc + cn + 1] = v1;
                }
                if (EPI & 8) {
                    if (cn + 1 < N) {
                        f16 h0, l0, h1, l1;
                        split1(v0, h0, l0);
                        split1(v1, h1, l1);
                        uint32_t hp = (uint32_t)__half_as_ushort(h0) | ((uint32_t)__half_as_ushort(h1) << 16);
                        *(uint32_t*)(Ch + (size_t)rr * ldc + cn) = hp;
                        if (!(EPI & 16)) {
                            uint32_t lp = (uint32_t)__half_as_ushort(l0) | ((uint32_t)__half_as_ushort(l1) << 16);
                            *(uint32_t*)(Cl + (size_t)rr * ldc + cn) = lp;
                        }
                    } else if (cn < N) {
                        f16 h0, l0;
                        split1(v0, h0, l0);
                        Ch[(size_t)rr * ldc + cn] = h0;
                        if (!(EPI & 16)) Cl[(size_t)rr * ldc + cn] = l0;
                    }
                }
            }
        }
    }
}

// ================= small kernels =================
__device__ __forceinline__ float warpReduceSum(float v) {
    #pragma unroll
    for (int o = 16; o > 0; o >>= 1) v += __shfl_down_sync(0xffffffffu, v, o);
    return v;
}
__device__ __forceinline__ float blockReduceSum(float v, float* smem) {
    __syncthreads();
    int lane = threadIdx.x & 31, wid = threadIdx.x >> 5;
    v = warpReduceSum(v);
    if (lane == 0) smem[wid] = v;
    __syncthreads();
    int nw = blockDim.x >> 5;
    float t = (threadIdx.x < nw) ? smem[threadIdx.x] : 0.0f;
    if (wid == 0) { t = warpReduceSum(t); if (lane == 0) smem[0] = t; }
    __syncthreads();
    return smem[0];
}

__global__ __launch_bounds__(256) void transpose_bf_kernel(
    const float* __restrict__ in, f16* __restrict__ oh, f16* __restrict__ ol)
{
    __shared__ float t[32][33];
    int bx = blockIdx.x * 32, by = blockIdx.y * 32;
    #pragma unroll
    for (int j = threadIdx.y; j < 32; j += 8)
        t[j][threadIdx.x] = in[(size_t)(by + j) * DIM + bx + threadIdx.x];
    __syncthreads();
    #pragma unroll
    for (int j = threadIdx.y; j < 32; j += 8) {
        float v = t[threadIdx.x][j];
        f16 h, l;
        split1(v, h, l);
        size_t o = (size_t)(bx + j) * DIM + by + threadIdx.x;
        oh[o] = h; ol[o] = l;
    }
}

__global__ __launch_bounds__(256) void split_pad_kernel(
    const float* __restrict__ src, f16* __restrict__ dh, f16* __restrict__ dl,
    int valid, int total)
{
    int i = (blockIdx.x * 256 + threadIdx.x) * 4;
    if (i >= total) return;
    float4 v;
    if (i + 3 < valid) v = *(const float4*)(src + i);
    else {
        v.x = (i + 0 < valid) ? src[i + 0] : 0.f;
        v.y = (i + 1 < valid) ? src[i + 1] : 0.f;
        v.z = (i + 2 < valid) ? src[i + 2] : 0.f;
        v.w = (i + 3 < valid) ? src[i + 3] : 0.f;
    }
    f16 h0, l0, h1, l1, h2, l2, h3, l3;
    split1(v.x, h0, l0); split1(v.y, h1, l1);
    split1(v.z, h2, l2); split1(v.w, h3, l3);
    uint2 hp = make_uint2(
        (uint32_t)__half_as_ushort(h0) | ((uint32_t)__half_as_ushort(h1) << 16),
        (uint32_t)__half_as_ushort(h2) | ((uint32_t)__half_as_ushort(h3) << 16));
    uint2 lp = make_uint2(
        (uint32_t)__half_as_ushort(l0) | ((uint32_t)__half_as_ushort(l1) << 16),
        (uint32_t)__half_as_ushort(l2) | ((uint32_t)__half_as_ushort(l3) << 16));
    *(uint2*)(dh + i) = hp;
    *(uint2*)(dl + i) = lp;
}

__global__ __launch_bounds__(256) void embed_norm_kernel(const float* __restrict__ emb) {
    int n = blockIdx.x, tid = threadIdx.x;
    if (n >= NEMB) {
        f16 z = __float2half_rn(0.f);
        for (int j = tid; j < DIM; j += 256) {
            wn_h[(size_t)n * DIM + j] = z;
            wn_l[(size_t)n * DIM + j] = z;
        }
        return;
    }
    const float* row = emb + (size_t)n * DIM;
    float s = 0.0f;
    for (int j = tid; j < DIM; j += 256) { float v = row[j]; s = fmaf(v, v, s); }
    __shared__ float red[32];
    s = blockReduceSum(s, red);
    float inv = 1.0f / fmaxf(sqrtf(s), 1e-12f);
    float c = 0.0f;
    for (int j = tid; j < DIM; j += 256) {
        float v = row[j] * inv;
        d_wn[(size_t)n * DIM + j] = v;
        f16 h, l;
        split1(v, h, l);
        wn_h[(size_t)n * DIM + j] = h;
        wn_l[(size_t)n * DIM + j] = l;
        c = fmaf(v, v, c);
    }
    c = blockReduceSum(c, red);
    if (tid == 0) d_c[n] = c;
}

__global__ __launch_bounds__(256) void feat_norm_kernel(const float* __restrict__ feat) {
    int b = blockIdx.x, tid = threadIdx.x;
    const float* row = feat + (size_t)b * DIM;
    float s = 0.0f;
    for (int j = tid; j < DIM; j += 256) { float v = row[j]; s = fmaf(v, v, s); }
    __shared__ float red[32];
    s = blockReduceSum(s, red);
    if (tid == 0) d_rinv[b] = 1.0f / fmaxf(sqrtf(s), 1e-12f);
}

__global__ __launch_bounds__(256) void argmin_kernel() {
    int b = blockIdx.x, tid = threadIdx.x;
    float r = d_rinv[b];
    float best = INFINITY, sec = INFINITY;
    int bi = 0x7fffffff;
    for (int n = tid; n < NEMB; n += 256) {
        float v = d_c[n] - 2.0f * r * d_S[(size_t)b * NEMB + n];
        if (v < best) { sec = best; best = v; bi = n; }
        else if (v < sec) sec = v;
    }
    __shared__ float rb[256], rs[256];
    __shared__ int ri[256];
    rb[tid] = best; rs[tid] = sec; ri[tid] = bi;
    __syncthreads();
    #pragma unroll
    for (int off = 128; off > 0; off >>= 1) {
        if (tid < off) {
            float b1 = rb[tid], s1 = rs[tid], b2 = rb[tid + off], s2 = rs[tid + off];
            int i1 = ri[tid], i2 = ri[tid + off];
            float nb, ns; int ni;
            if (b2 < b1)      { nb = b2; ni = i2; ns = fminf(b1, s2); }
            else if (b1 < b2) { nb = b1; ni = i1; ns = fminf(b2, s1); }
            else              { nb = b1; ni = min(i1, i2); ns = b2; }
            rb[tid] = nb; rs[tid] = ns; ri[tid] = ni;
        }
        __syncthreads();
    }
    if (tid == 0) { d_bidx[b] = ri[0]; d_gap[b] = rs[0] - rb[0]; }
}

__global__ __launch_bounds__(256) void refine_gather_kernel(
    const float* __restrict__ emb, const float* __restrict__ feat,
    float* __restrict__ outq, float* __restrict__ outi)
{
    int b = blockIdx.x, tid = threadIdx.x;
    int idx = d_bidx[b];
    if (d_gap[b] < 1e-3f) {
        __shared__ float sf[DIM];
        const float* f = feat + (size_t)b * DIM;
        for (int j = tid; j < DIM; j += 256) sf[j] = f[j];
        __syncthreads();
        float r = d_rinv[b];
        int wid = tid >> 5, lane = tid & 31;
        float best = INFINITY; int bi = 0x7fffffff;
        for (int n = wid; n < NEMB; n += 8) {
            const float* w = d_wn + (size_t)n * DIM;
            float s = 0.0f;
            for (int j = lane; j < DIM; j += 32) s = fmaf(sf[j], w[j], s);
            s = warpReduceSum(s);
            s = __shfl_sync(0xffffffffu, s, 0);
            float v = d_c[n] - 2.0f * r * s;
            if (v < best) { best = v; bi = n; }
        }
        __shared__ float wb[8]; __shared__ int wi[8];
        if (lane == 0) { wb[wid] = best; wi[wid] = bi; }
        __syncthreads();
        if (tid == 0) {
            float bb = wb[0]; int ii = wi[0];
            for (int w = 1; w < 8; w++)
                if (wb[w] < bb || (wb[w] == bb && wi[w] < ii)) { bb = wb[w]; ii = wi[w]; }
            wi[0] = ii;
        }
        __syncthreads();
        idx = wi[0];
        if (tid == 0) d_bidx[b] = idx;
    }
    const float* src = emb + (size_t)idx * DIM;
    float* dst = outq + (size_t)b * DIM;
    for (int j = tid; j < DIM; j += 256) dst[j] = src[j];
    if (tid == 0) outi[b] = (float)idx;
}

__global__ __launch_bounds__(256) void diag_kernel(const float* __restrict__ emb) {
    int n = blockIdx.x, tid = threadIdx.x;
    const float* y = d_Y + (size_t)n * DIM;
    const float* e = emb + (size_t)n * DIM;
    float s = 0.0f;
    for (int j = tid; j < DIM; j += 256) s = fmaf(y[j], e[j], s);
    __shared__ float red[32];
    s = blockReduceSum(s, red);
    if (tid == 0) d_diag[n] = s;
}

__global__ __launch_bounds__(256) void attn_mix2_kernel(
    const float* __restrict__ feat, const float* __restrict__ outq)
{
    int b = blockIdx.x, tid = threadIdx.x;
    int idx = d_bidx[b];
    const float* t1 = feat + (size_t)b * DIM;
    const float* t0 = outq + (size_t)b * DIM;
    const float* yr = d_Y + (size_t)idx * DIM;
    const float* zr = d_Z + (size_t)idx * DIM;
    const float* wr = d_W + (size_t)b * DIM;
    float s01 = 0, s10 = 0, s11 = 0;
    for (int j = tid; j < DIM; j += 256) {
        float f = t1[j];
        s01 = fmaf(yr[j], f, s01);
        s10 = fmaf(zr[j], f, s10);
        s11 = fmaf(wr[j], f, s11);
    }
    __shared__ float red[32];
    s01 = blockReduceSum(s01, red);
    s10 = blockReduceSum(s10, red);
    s11 = blockReduceSum(s11, red);
    float s00 = d_diag[idx];
    float m0 = fmaxf(s00, s10);
    float e00 = expf(s00 - m0), e10 = expf(s10 - m0);
    float iv0 = 1.0f / (e00 + e10);
    float a00 = e00 * iv0, a10 = e10 * iv0;
    float m1 = fmaxf(s01, s11);
    float e01 = expf(s01 - m1), e11 = expf(s11 - m1);
    float iv1 = 1.0f / (e01 + e11);
    float a01 = e01 * iv1, a11 = e11 * iv1;
    size_t go = (size_t)b * 2 * DIM;
    for (int j = tid; j < DIM; j += 256) {
        float v0 = t0[j], v1 = t1[j];
        g_h[go + j]       = __float2half_rn(fmaf(a00, v0, a10 * v1));
        g_h[go + DIM + j] = __float2half_rn(fmaf(a01, v0, a11 * v1));
    }
}

// ================= launch =================
extern "C" void kernel_launch(void* const* d_in, const int* in_sizes, int n_in,
                              void* d_out, int out_size)
{
    const float* feat = (const float*)d_in[0];
    const float* emb  = (const float*)d_in[1];
    const float* Kw   = (const float*)d_in[2];
    const float* Qw   = (const float*)d_in[3];
    const float* Vw   = (const float*)d_in[4];
    const float* fw   = (const float*)d_in[5];
    const float* fb   = (const float*)d_in[6];
    const float* fcw  = (const float*)d_in[7];
    const float* fcb  = (const float*)d_in[8];

    float* out  = (float*)d_out;
    float* outq = out;
    float* outp = out + (size_t)BATCH * DIM;
    float* outi = outp + (size_t)BATCH * NCLS;

    float *S, *Mm, *W, *Y, *Z;
    f16 *p_feath, *p_featl, *p_embh, *p_embl, *p_wnh, *p_wnl;
    f16 *p_kwth, *p_kwtl, *p_qwth, *p_qwtl, *p_vwth, *p_vwtl;
    f16 *p_mh, *p_ml, *p_mth, *p_mtl, *p_fwh, *p_fwl, *p_fcwh, *p_fcwl;
    f16 *p_pth, *p_ptl, *p_gh, *p_hh;
    cudaGetSymbolAddress((void**)&S,   d_S);
    cudaGetSymbolAddress((void**)&Mm,  d_M);
    cudaGetSymbolAddress((void**)&W,   d_W);
    cudaGetSymbolAddress((void**)&Y,   d_Y);
    cudaGetSymbolAddress((void**)&Z,   d_Z);
    cudaGetSymbolAddress((void**)&p_feath, feat_h); cudaGetSymbolAddress((void**)&p_featl, feat_l);
    cudaGetSymbolAddress((void**)&p_embh,  emb_h);  cudaGetSymbolAddress((void**)&p_embl,  emb_l);
    cudaGetSymbolAddress((void**)&p_wnh,   wn_h);   cudaGetSymbolAddress((void**)&p_wnl,   wn_l);
    cudaGetSymbolAddress((void**)&p_kwth,  kwt_h);  cudaGetSymbolAddress((void**)&p_kwtl,  kwt_l);
    cudaGetSymbolAddress((void**)&p_qwth,  qwt_h);  cudaGetSymbolAddress((void**)&p_qwtl,  qwt_l);
    cudaGetSymbolAddress((void**)&p_vwth,  vwt_h);  cudaGetSymbolAddress((void**)&p_vwtl,  vwt_l);
    cudaGetSymbolAddress((void**)&p_mh,    m_h);    cudaGetSymbolAddress((void**)&p_ml,    m_l);
    cudaGetSymbolAddress((void**)&p_mth,   mt_h);   cudaGetSymbolAddress((void**)&p_mtl,   mt_l);
    cudaGetSymbolAddress((void**)&p_fwh,   fw_h);   cudaGetSymbolAddress((void**)&p_fwl,   fw_l);
    cudaGetSymbolAddress((void**)&p_fcwh,  fcw_h);  cudaGetSymbolAddress((void**)&p_fcwl,  fcw_l);
    cudaGetSymbolAddress((void**)&p_pth,   pt_h);   cudaGetSymbolAddress((void**)&p_ptl,   pt_l);
    cudaGetSymbolAddress((void**)&p_gh,    g_h);
    cudaGetSymbolAddress((void**)&p_hh,    h_h);

    cudaFuncSetAttribute((const void*)tc_gemm<4, 1>,  cudaFuncAttributeMaxDynamicSharedMemorySize, SMEM_BYTES);
    cudaFuncSetAttribute((const void*)tc_gemm<4, 3>,  cudaFuncAttributeMaxDynamicSharedMemorySize, SMEM_BYTES);
    cudaFuncSetAttribute((const void*)tc_gemm<12, 3>, cudaFuncAttributeMaxDynamicSharedMemorySize, SMEM_BYTES);
    cudaFuncSetAttribute((const void*)tc_gemm<8, 2>,  cudaFuncAttributeMaxDynamicSharedMemorySize, SMEM_BYTES);
    cudaFuncSetAttribute((const void*)tc_gemm<27, 2>, cudaFuncAttributeMaxDynamicSharedMemorySize, SMEM_BYTES);
    cudaFuncSetAttribute((const void*)tc_gemm<5, 2>,  cudaFuncAttributeMaxDynamicSharedMemorySize, SMEM_BYTES);

    cudaStream_t s1 = g_ctx.s1, s2 = g_ctx.s2;
    dim3 tb(32, 8);
    dim3 tg(DIM / 32, DIM / 32);

    // ---- default stream prefix ----
    split_pad_kernel<<<(BATCH * DIM / 4 + 255) / 256, 256>>>(feat, p_feath, p_featl, BATCH * DIM, BATCH * DIM);
    embed_norm_kernel<<<NPAD, 256>>>(emb);
    split_pad_kernel<<<(NPAD * DIM / 4 + 255) / 256, 256>>>(emb, p_embh, p_embl, NEMB * DIM, NPAD * DIM);
    cudaEventRecord(g_ctx.eFork, 0);

    // ---- s1: M chain -> Y -> diag ----
    cudaStreamWaitEvent(s1, g_ctx.eFork, 0);
    transpose_bf_kernel<<<tg, tb, 0, s1>>>(Kw, p_kwth, p_kwtl);
    transpose_bf_kernel<<<tg, tb, 0, s1>>>(Qw, p_qwth, p_qwtl);
    tc_gemm<12, 3><<<dim3(DIM / BN, DIM / BM), 256, SMEM_BYTES, s1>>>(
        p_kwth, p_kwtl, p_qwth, p_qwtl, nullptr, Mm, p_mh, p_ml,
        DIM, DIM, DIM, DIM, DIM, DIM);
    cudaEventRecord(g_ctx.eM, s1);
    transpose_bf_kernel<<<tg, tb, 0, s1>>>(Mm, p_mth, p_mtl);
    tc_gemm<4, 3><<<dim3(DIM / BN, NPAD / BM), 256, SMEM_BYTES, s1>>>(
        p_embh, p_embl, p_mth, p_mtl, nullptr, Y, nullptr, nullptr,
        NEMB, DIM, DIM, DIM, DIM, DIM);
    diag_kernel<<<NEMB, 256, 0, s1>>>(emb);
    cudaEventRecord(g_ctx.e1, s1);

    // ---- s2: Vw/fw/fcw prep -> Z -> PT ----
    cudaStreamWaitEvent(s2, g_ctx.eFork, 0);
    transpose_bf_kernel<<<tg, tb, 0, s2>>>(Vw, p_vwth, p_vwtl);
    split_pad_kernel<<<(DIM * 2 * DIM / 4 + 255) / 256, 256, 0, s2>>>(fw, p_fwh, p_fwl, DIM * 2 * DIM, DIM * 2 * DIM);
    split_pad_kernel<<<(NPAD * DIM / 4 + 255) / 256, 256, 0, s2>>>(fcw, p_fcwh, p_fcwl, NCLS * DIM, NPAD * DIM);
    cudaStreamWaitEvent(s2, g_ctx.eM, 0);
    tc_gemm<4, 3><<<dim3(DIM / BN, NPAD / BM), 256, SMEM_BYTES, s2>>>(
        p_embh, p_embl, p_mh, p_ml, nullptr, Z, nullptr, nullptr,
        NEMB, DIM, DIM, DIM, DIM, DIM);
    tc_gemm<8, 2><<<dim3(DIM / BN, DIM / BM), 256, SMEM_BYTES, s2>>>(
        p_fwh,       nullptr, p_vwth, p_vwtl, nullptr, nullptr, p_pth,       p_ptl,
        DIM, DIM, DIM, 2 * DIM, DIM, 2 * DIM);
    tc_gemm<8, 2><<<dim3(DIM / BN, DIM / BM), 256, SMEM_BYTES, s2>>>(
        p_fwh + DIM, nullptr, p_vwth, p_vwtl, nullptr, nullptr, p_pth + DIM, p_ptl + DIM,
        DIM, DIM, DIM, 2 * DIM, DIM, 2 * DIM);
    cudaEventRecord(g_ctx.e2, s2);

    // ---- default stream: S chain (1-product) -> W ----
    feat_norm_kernel<<<BATCH, 256>>>(feat);
    tc_gemm<4, 1><<<dim3(NPAD / BN, BATCH / BM), 256, SMEM_BYTES>>>(
        p_feath, nullptr, p_wnh, nullptr, nullptr, S, nullptr, nullptr,
        BATCH, NEMB, DIM, DIM, DIM, NEMB);
    argmin_kernel<<<BATCH, 256>>>();
    refine_gather_kernel<<<BATCH, 256>>>(emb, feat, outq, outi);
    cudaStreamWaitEvent(0, g_ctx.eM, 0);
    tc_gemm<4, 3><<<dim3(DIM / BN, BATCH / BM), 256, SMEM_BYTES>>>(
        p_feath, p_featl, p_mh, p_ml, nullptr, W, nullptr, nullptr,
        BATCH, DIM, DIM, DIM, DIM, DIM);

    // ---- join, then tail chain ----
    cudaStreamWaitEvent(0, g_ctx.e1, 0);
    cudaStreamWaitEvent(0, g_ctx.e2, 0);
    attn_mix2_kernel<<<BATCH, 256>>>(feat, outq);
    tc_gemm<27, 2><<<dim3(DIM / BN, BATCH / BM), 256, SMEM_BYTES>>>(
        p_gh, nullptr, p_pth, p_ptl, fb, nullptr, p_hh, nullptr,
        BATCH, DIM, 2 * DIM, 2 * DIM, 2 * DIM, DIM);
    tc_gemm<5, 2><<<dim3(NPAD / BN, BATCH / BM), 256, SMEM_BYTES>>>(
        p_hh, nullptr, p_fcwh, p_fcwl, fcb, outp, nullptr, nullptr,
        BATCH, NCLS, DIM, DIM, DIM, NCLS);
}

// round 10
// speedup vs baseline: 1.3654x; 1.2149x over previous
#include <cuda_runtime.h>
#include <cuda_fp16.h>
#include <math.h>
#include <stdint.h>

#define BATCH 8192
#define DIM   2048
#define NEMB  1000
#define NCLS  1000
#define NPAD  1024

typedef __half f16;

// ---------------- fp32 scratch ----------------
__device__ float d_wn[NEMB * DIM];
__device__ float d_c[NEMB];
__device__ float d_rinv[BATCH];
__device__ float d_S[BATCH * NEMB];
__device__ float d_M[DIM * DIM];
__device__ float d_W[BATCH * DIM];
__device__ float d_Y[NEMB * DIM];
__device__ float d_Z[NEMB * DIM];
__device__ float d_diag[NEMB];
__device__ int   d_bidx[BATCH];
__device__ float d_gap[BATCH];

// ---------------- fp16 hi/lo planes ----------------
__device__ f16 feat_h[BATCH * DIM],  feat_l[BATCH * DIM];
__device__ f16 emb_h[NPAD * DIM],    emb_l[NPAD * DIM];
__device__ f16 wn_h[NPAD * DIM],     wn_l[NPAD * DIM];
__device__ f16 kwt_h[DIM * DIM],     kwt_l[DIM * DIM];
__device__ f16 qwt_h[DIM * DIM],     qwt_l[DIM * DIM];
__device__ f16 vwt_h[DIM * DIM],     vwt_l[DIM * DIM];
__device__ f16 m_h[DIM * DIM],       m_l[DIM * DIM];
__device__ f16 mt_h[DIM * DIM],      mt_l[DIM * DIM];
__device__ f16 fw_h[DIM * 2 * DIM],  fw_l[DIM * 2 * DIM];
__device__ f16 fcw_h[NPAD * DIM],    fcw_l[NPAD * DIM];
__device__ f16 pt_h[DIM * 2 * DIM];
__device__ f16 g_h[BATCH * 2 * DIM];
__device__ f16 h_h[BATCH * DIM];

// ---------------- streams/events ----------------
namespace {
struct Ctx {
    cudaStream_t s1, s2;
    cudaEvent_t eFork, eM, e1, e2;
    Ctx() {
        cudaStreamCreateWithFlags(&s1, cudaStreamNonBlocking);
        cudaStreamCreateWithFlags(&s2, cudaStreamNonBlocking);
        cudaEventCreateWithFlags(&eFork, cudaEventDisableTiming);
        cudaEventCreateWithFlags(&eM,    cudaEventDisableTiming);
        cudaEventCreateWithFlags(&e1,    cudaEventDisableTiming);
        cudaEventCreateWithFlags(&e2,    cudaEventDisableTiming);
    }
};
Ctx g_ctx;
}

// ---------------- helpers ----------------
__device__ __forceinline__ uint32_t smem_to_u32(const void* p) {
    uint32_t a;
    asm("{ .reg .u64 t; cvta.to.shared.u64 t, %1; cvt.u32.u64 %0, t; }" : "=r"(a) : "l"(p));
    return a;
}
__device__ __forceinline__ void split1(float v, f16& h, f16& l) {
    h = __float2half_rn(v);
    l = __float2half_rn(v - __half2float(h));
}
__device__ __forceinline__ void ldsm4(uint32_t* r, uint32_t addr) {
    asm volatile("ldmatrix.sync.aligned.m8n8.x4.shared.b16 {%0,%1,%2,%3}, [%4];"
        : "=r"(r[0]), "=r"(r[1]), "=r"(r[2]), "=r"(r[3]) : "r"(addr));
}
__device__ __forceinline__ void ldsm2(uint32_t* r, uint32_t addr) {
    asm volatile("ldmatrix.sync.aligned.m8n8.x2.shared.b16 {%0,%1}, [%2];"
        : "=r"(r[0]), "=r"(r[1]) : "r"(addr));
}
__device__ __forceinline__ void mma16816(float* d, const uint32_t* a, const uint32_t* b) {
    asm volatile("mma.sync.aligned.m16n8k16.row.col.f32.f16.f16.f32 "
        "{%0,%1,%2,%3},{%4,%5,%6,%7},{%8,%9},{%0,%1,%2,%3};"
        : "+f"(d[0]), "+f"(d[1]), "+f"(d[2]), "+f"(d[3])
        : "r"(a[0]), "r"(a[1]), "r"(a[2]), "r"(a[3]), "r"(b[0]), "r"(b[1]));
}
__device__ __forceinline__ void cpa16(uint32_t dst, const void* src) {
    asm volatile("cp.async.cg.shared.global [%0], [%1], 16;" :: "r"(dst), "l"(src));
}
#define CP_COMMIT() asm volatile("cp.async.commit_group;" ::: "memory")
#define CP_WAIT(n)  asm volatile("cp.async.wait_group %0;" :: "n"(n) : "memory")

// ================= tensor-core GEMM (pre-split fp16, NT, f32 acc) =================
// NPROD=1: Ah*Bh. NPROD=2: + Ah*Bl. NPROD=3: + Al*Bh.
// EPI bits: 1=bias, 2=relu, 4=write f32, 8=write f16 planes, 16=hi plane only
#define BM 128
#define BN 128
#define STAGE_BYTES 32768
#define SMEM_BYTES  (2 * STAGE_BYTES)

template<int EPI, int NPROD>
__global__ __launch_bounds__(256, 2)
void tc_gemm(const f16* __restrict__ Ah, const f16* __restrict__ Al,
             const f16* __restrict__ Bh, const f16* __restrict__ Bl,
             const float* __restrict__ bias,
             float* __restrict__ Cf, f16* __restrict__ Ch, f16* __restrict__ Cl,
             int M, int N, int K, int lda, int ldb, int ldc)
{
    extern __shared__ char smem[];
    const int tid  = threadIdx.x;
    const int lane = tid & 31;
    const int wid  = tid >> 5;
    const int wm   = (wid >> 2) << 6;
    const int wn   = (wid & 3) << 5;
    const int bm   = blockIdx.y * BM;
    const int bn   = blockIdx.x * BN;
    const uint32_t sb = smem_to_u32(smem);

    float acc[4][4][4];
    #pragma unroll
    for (int i = 0; i < 4; i++)
        #pragma unroll
        for (int j = 0; j < 4; j++)
            #pragma unroll
            for (int k = 0; k < 4; k++) acc[i][j][k] = 0.f;

    auto copy = [&](int s, int k0) {
        uint32_t base = sb + s * STAGE_BYTES;
        #pragma unroll
        for (int i = 0; i < 4; i++) {
            int id = (i << 8) + tid;
            int row = id >> 3, rem = id & 7, pl = rem >> 2, u = rem & 3;
            if (NPROD == 3 || pl == 0) {
                const f16* src = (pl ? Al : Ah) + (size_t)(bm + row) * lda + k0 + (u << 3);
                uint32_t dst = base + row * 128 + ((((u ^ (row & 7))) ^ (pl << 2)) << 4);
                cpa16(dst, src);
            }
        }
        #pragma unroll
        for (int i = 0; i < 4; i++) {
            int id = (i << 8) + tid;
            int row = id >> 3, rem = id & 7, pl = rem >> 2, u = rem & 3;
            if (NPROD >= 2 || pl == 0) {
                const f16* src = (pl ? Bl : Bh) + (size_t)(bn + row) * ldb + k0 + (u << 3);
                uint32_t dst = base + 16384 + row * 128 + ((((u ^ (row & 7))) ^ (pl << 2)) << 4);
                cpa16(dst, src);
            }
        }
    };

    copy(0, 0);
    CP_COMMIT();

    const int nc = K >> 5;
    for (int c = 0; c < nc; c++) {
        int s = c & 1;
        if (c + 1 < nc) {
            copy(s ^ 1, (c + 1) << 5);
            CP_COMMIT();
            CP_WAIT(1);
        } else {
            CP_WAIT(0);
        }
        __syncthreads();

        uint32_t a_s = sb + s * STAGE_BYTES;
        uint32_t b_s = a_s + 16384;
        #pragma unroll
        for (int h = 0; h < 2; h++) {
            uint32_t bhf[4][2], blf[4][2];
            #pragma unroll
            for (int nt = 0; nt < 4; nt++) {
                int r = wn + (nt << 3) + (lane & 7);
                int lu = (h << 1) + ((lane >> 3) & 1);
                uint32_t ad = b_s + r * 128 + ((uint32_t)(lu ^ (r & 7)) << 4);
                ldsm2(bhf[nt], ad);
                if (NPROD >= 2) ldsm2(blf[nt], ad ^ 64u);
            }
            #pragma unroll
            for (int mt = 0; mt < 4; mt++) {
                int g = lane >> 3;
                int r = wm + (mt << 4) + ((g & 1) << 3) + (lane & 7);
                int lu = (h << 1) + (g >> 1);
                uint32_t ad = a_s + r * 128 + ((uint32_t)(lu ^ (r & 7)) << 4);
                uint32_t af[4];
                ldsm4(af, ad);                       // A hi
                #pragma unroll
                for (int nt = 0; nt < 4; nt++) mma16816(acc[mt][nt], af, bhf[nt]);
                if (NPROD >= 2) {
                    #pragma unroll
                    for (int nt = 0; nt < 4; nt++) mma16816(acc[mt][nt], af, blf[nt]);
                }
                if (NPROD == 3) {
                    ldsm4(af, ad ^ 64u);             // A lo
                    #pragma unroll
                    for (int nt = 0; nt < 4; nt++) mma16816(acc[mt][nt], af, bhf[nt]);
                }
            }
        }
        __syncthreads();
    }

    // epilogue
    #pragma unroll
    for (int mt = 0; mt < 4; mt++) {
        int r0 = bm + wm + (mt << 4) + (lane >> 2);
        #pragma unroll
        for (int half = 0; half < 2; half++) {
            int rr = r0 + half * 8;
            if (rr >= M) continue;
            #pragma unroll
            for (int nt = 0; nt < 4; nt++) {
                int cn = bn + wn + (nt << 3) + ((lane & 3) << 1);
                float v0 = acc[mt][nt][half * 2 + 0];
                float v1 = acc[mt][nt][half * 2 + 1];
                if (EPI & 1) {
                    if (cn < N)     v0 += bias[cn];
                    if (cn + 1 < N) v1 += bias[cn + 1];
                }
                if (EPI & 2) { v0 = fmaxf(v0, 0.f); v1 = fmaxf(v1, 0.f); }
                if (EPI & 4) {
                    if (cn < N)     Cf[(size_t)rr * ldc + cn] = v0;
                    if (cn + 1 < N) Cf[(size_t)rr * ldc + cn + 1] = v1;
                }
                if (EPI & 8) {
                    if (cn + 1 < N) {
                        f16 h0, l0, h1, l1;
                        split1(v0, h0, l0);
                        split1(v1, h1, l1);
                        uint32_t hp = (uint32_t)__half_as_ushort(h0) | ((uint32_t)__half_as_ushort(h1) << 16);
                        *(uint32_t*)(Ch + (size_t)rr * ldc + cn) = hp;
                        if (!(EPI & 16)) {
                            uint32_t lp = (uint32_t)__half_as_ushort(l0) | ((uint32_t)__half_as_ushort(l1) << 16);
                            *(uint32_t*)(Cl + (size_t)rr * ldc + cn) = lp;
                        }
                    } else if (cn < N) {
                        f16 h0, l0;
                        split1(v0, h0, l0);
                        Ch[(size_t)rr * ldc + cn] = h0;
                        if (!(EPI & 16)) Cl[(size_t)rr * ldc + cn] = l0;
                    }
                }
            }
        }
    }
}

// ================= small kernels =================
__device__ __forceinline__ float warpReduceSum(float v) {
    #pragma unroll
    for (int o = 16; o > 0; o >>= 1) v += __shfl_down_sync(0xffffffffu, v, o);
    return v;
}
__device__ __forceinline__ float blockReduceSum(float v, float* smem) {
    __syncthreads();
    int lane = threadIdx.x & 31, wid = threadIdx.x >> 5;
    v = warpReduceSum(v);
    if (lane == 0) smem[wid] = v;
    __syncthreads();
    int nw = blockDim.x >> 5;
    float t = (threadIdx.x < nw) ? smem[threadIdx.x] : 0.0f;
    if (wid == 0) { t = warpReduceSum(t); if (lane == 0) smem[0] = t; }
    __syncthreads();
    return smem[0];
}

__global__ __launch_bounds__(256) void transpose_bf_kernel(
    const float* __restrict__ in, f16* __restrict__ oh, f16* __restrict__ ol)
{
    __shared__ float t[32][33];
    int bx = blockIdx.x * 32, by = blockIdx.y * 32;
    #pragma unroll
    for (int j = threadIdx.y; j < 32; j += 8)
        t[j][threadIdx.x] = in[(size_t)(by + j) * DIM + bx + threadIdx.x];
    __syncthreads();
    #pragma unroll
    for (int j = threadIdx.y; j < 32; j += 8) {
        float v = t[threadIdx.x][j];
        f16 h, l;
        split1(v, h, l);
        size_t o = (size_t)(bx + j) * DIM + by + threadIdx.x;
        oh[o] = h; ol[o] = l;
    }
}

__global__ __launch_bounds__(256) void split_pad_kernel(
    const float* __restrict__ src, f16* __restrict__ dh, f16* __restrict__ dl,
    int valid, int total)
{
    int i = (blockIdx.x * 256 + threadIdx.x) * 4;
    if (i >= total) return;
    float4 v;
    if (i + 3 < valid) v = *(const float4*)(src + i);
    else {
        v.x = (i + 0 < valid) ? src[i + 0] : 0.f;
        v.y = (i + 1 < valid) ? src[i + 1] : 0.f;
        v.z = (i + 2 < valid) ? src[i + 2] : 0.f;
        v.w = (i + 3 < valid) ? src[i + 3] : 0.f;
    }
    f16 h0, l0, h1, l1, h2, l2, h3, l3;
    split1(v.x, h0, l0); split1(v.y, h1, l1);
    split1(v.z, h2, l2); split1(v.w, h3, l3);
    uint2 hp = make_uint2(
        (uint32_t)__half_as_ushort(h0) | ((uint32_t)__half_as_ushort(h1) << 16),
        (uint32_t)__half_as_ushort(h2) | ((uint32_t)__half_as_ushort(h3) << 16));
    uint2 lp = make_uint2(
        (uint32_t)__half_as_ushort(l0) | ((uint32_t)__half_as_ushort(l1) << 16),
        (uint32_t)__half_as_ushort(l2) | ((uint32_t)__half_as_ushort(l3) << 16));
    *(uint2*)(dh + i) = hp;
    *(uint2*)(dl + i) = lp;
}

__global__ __launch_bounds__(256) void embed_norm_kernel(const float* __restrict__ emb) {
    int n = blockIdx.x, tid = threadIdx.x;
    if (n >= NEMB) {
        f16 z = __float2half_rn(0.f);
        for (int j = tid; j < DIM; j += 256) {
            wn_h[(size_t)n * DIM + j] = z;
            wn_l[(size_t)n * DIM + j] = z;
        }
        return;
    }
    const float* row = emb + (size_t)n * DIM;
    float s = 0.0f;
    for (int j = tid; j < DIM; j += 256) { float v = row[j]; s = fmaf(v, v, s); }
    __shared__ float red[32];
    s = blockReduceSum(s, red);
    float inv = 1.0f / fmaxf(sqrtf(s), 1e-12f);
    float c = 0.0f;
    for (int j = tid; j < DIM; j += 256) {
        float v = row[j] * inv;
        d_wn[(size_t)n * DIM + j] = v;
        f16 h, l;
        split1(v, h, l);
        wn_h[(size_t)n * DIM + j] = h;
        wn_l[(size_t)n * DIM + j] = l;
        c = fmaf(v, v, c);
    }
    c = blockReduceSum(c, red);
    if (tid == 0) d_c[n] = c;
}

__global__ __launch_bounds__(256) void feat_norm_kernel(const float* __restrict__ feat) {
    int b = blockIdx.x, tid = threadIdx.x;
    const float* row = feat + (size_t)b * DIM;
    float s = 0.0f;
    for (int j = tid; j < DIM; j += 256) { float v = row[j]; s = fmaf(v, v, s); }
    __shared__ float red[32];
    s = blockReduceSum(s, red);
    if (tid == 0) d_rinv[b] = 1.0f / fmaxf(sqrtf(s), 1e-12f);
}

__global__ __launch_bounds__(256) void argmin_kernel() {
    int b = blockIdx.x, tid = threadIdx.x;
    float r = d_rinv[b];
    float best = INFINITY, sec = INFINITY;
    int bi = 0x7fffffff;
    for (int n = tid; n < NEMB; n += 256) {
        float v = d_c[n] - 2.0f * r * d_S[(size_t)b * NEMB + n];
        if (v < best) { sec = best; best = v; bi = n; }
        else if (v < sec) sec = v;
    }
    __shared__ float rb[256], rs[256];
    __shared__ int ri[256];
    rb[tid] = best; rs[tid] = sec; ri[tid] = bi;
    __syncthreads();
    #pragma unroll
    for (int off = 128; off > 0; off >>= 1) {
        if (tid < off) {
            float b1 = rb[tid], s1 = rs[tid], b2 = rb[tid + off], s2 = rs[tid + off];
            int i1 = ri[tid], i2 = ri[tid + off];
            float nb, ns; int ni;
            if (b2 < b1)      { nb = b2; ni = i2; ns = fminf(b1, s2); }
            else if (b1 < b2) { nb = b1; ni = i1; ns = fminf(b2, s1); }
            else              { nb = b1; ni = min(i1, i2); ns = b2; }
            rb[tid] = nb; rs[tid] = ns; ri[tid] = ni;
        }
        __syncthreads();
    }
    if (tid == 0) { d_bidx[b] = ri[0]; d_gap[b] = rs[0] - rb[0]; }
}

__global__ __launch_bounds__(256) void refine_gather_kernel(
    const float* __restrict__ emb, const float* __restrict__ feat,
    float* __restrict__ outq, float* __restrict__ outi)
{
    int b = blockIdx.x, tid = threadIdx.x;
    int idx = d_bidx[b];
    if (d_gap[b] < 1e-3f) {
        __shared__ float sf[DIM];
        const float* f = feat + (size_t)b * DIM;
        for (int j = tid; j < DIM; j += 256) sf[j] = f[j];
        __syncthreads();
        float r = d_rinv[b];
        int wid = tid >> 5, lane = tid & 31;
        float best = INFINITY; int bi = 0x7fffffff;
        for (int n = wid; n < NEMB; n += 8) {
            const float* w = d_wn + (size_t)n * DIM;
            float s = 0.0f;
            for (int j = lane; j < DIM; j += 32) s = fmaf(sf[j], w[j], s);
            s = warpReduceSum(s);
            s = __shfl_sync(0xffffffffu, s, 0);
            float v = d_c[n] - 2.0f * r * s;
            if (v < best) { best = v; bi = n; }
        }
        __shared__ float wb[8]; __shared__ int wi[8];
        if (lane == 0) { wb[wid] = best; wi[wid] = bi; }
        __syncthreads();
        if (tid == 0) {
            float bb = wb[0]; int ii = wi[0];
            for (int w = 1; w < 8; w++)
                if (wb[w] < bb || (wb[w] == bb && wi[w] < ii)) { bb = wb[w]; ii = wi[w]; }
            wi[0] = ii;
        }
        __syncthreads();
        idx = wi[0];
        if (tid == 0) d_bidx[b] = idx;
    }
    const float* src = emb + (size_t)idx * DIM;
    float* dst = outq + (size_t)b * DIM;
    for (int j = tid; j < DIM; j += 256) dst[j] = src[j];
    if (tid == 0) outi[b] = (float)idx;
}

__global__ __launch_bounds__(256) void diag_kernel(const float* __restrict__ emb) {
    int n = blockIdx.x, tid = threadIdx.x;
    const float* y = d_Y + (size_t)n * DIM;
    const float* e = emb + (size_t)n * DIM;
    float s = 0.0f;
    for (int j = tid; j < DIM; j += 256) s = fmaf(y[j], e[j], s);
    __shared__ float red[32];
    s = blockReduceSum(s, red);
    if (tid == 0) d_diag[n] = s;
}

__global__ __launch_bounds__(256) void attn_mix2_kernel(
    const float* __restrict__ feat, const float* __restrict__ outq)
{
    int b = blockIdx.x, tid = threadIdx.x;
    int idx = d_bidx[b];
    const float* t1 = feat + (size_t)b * DIM;
    const float* t0 = outq + (size_t)b * DIM;
    const float* yr = d_Y + (size_t)idx * DIM;
    const float* zr = d_Z + (size_t)idx * DIM;
    const float* wr = d_W + (size_t)b * DIM;
    float s01 = 0, s10 = 0, s11 = 0;
    for (int j = tid; j < DIM; j += 256) {
        float f = t1[j];
        s01 = fmaf(yr[j], f, s01);
        s10 = fmaf(zr[j], f, s10);
        s11 = fmaf(wr[j], f, s11);
    }
    __shared__ float red[32];
    s01 = blockReduceSum(s01, red);
    s10 = blockReduceSum(s10, red);
    s11 = blockReduceSum(s11, red);
    float s00 = d_diag[idx];
    float m0 = fmaxf(s00, s10);
    float e00 = expf(s00 - m0), e10 = expf(s10 - m0);
    float iv0 = 1.0f / (e00 + e10);
    float a00 = e00 * iv0, a10 = e10 * iv0;
    float m1 = fmaxf(s01, s11);
    float e01 = expf(s01 - m1), e11 = expf(s11 - m1);
    float iv1 = 1.0f / (e01 + e11);
    float a01 = e01 * iv1, a11 = e11 * iv1;
    size_t go = (size_t)b * 2 * DIM;
    for (int j = tid; j < DIM; j += 256) {
        float v0 = t0[j], v1 = t1[j];
        g_h[go + j]       = __float2half_rn(fmaf(a00, v0, a10 * v1));
        g_h[go + DIM + j] = __float2half_rn(fmaf(a01, v0, a11 * v1));
    }
}

// ================= launch =================
extern "C" void kernel_launch(void* const* d_in, const int* in_sizes, int n_in,
                              void* d_out, int out_size)
{
    const float* feat = (const float*)d_in[0];
    const float* emb  = (const float*)d_in[1];
    const float* Kw   = (const float*)d_in[2];
    const float* Qw   = (const float*)d_in[3];
    const float* Vw   = (const float*)d_in[4];
    const float* fw   = (const float*)d_in[5];
    const float* fb   = (const float*)d_in[6];
    const float* fcw  = (const float*)d_in[7];
    const float* fcb  = (const float*)d_in[8];

    float* out  = (float*)d_out;
    float* outq = out;
    float* outp = out + (size_t)BATCH * DIM;
    float* outi = outp + (size_t)BATCH * NCLS;

    float *S, *Mm, *W, *Y, *Z;
    f16 *p_feath, *p_featl, *p_embh, *p_embl, *p_wnh, *p_wnl;
    f16 *p_kwth, *p_kwtl, *p_qwth, *p_qwtl, *p_vwth, *p_vwtl;
    f16 *p_mh, *p_ml, *p_mth, *p_mtl, *p_fwh, *p_fwl, *p_fcwh, *p_fcwl;
    f16 *p_pth, *p_gh, *p_hh;
    cudaGetSymbolAddress((void**)&S,   d_S);
    cudaGetSymbolAddress((void**)&Mm,  d_M);
    cudaGetSymbolAddress((void**)&W,   d_W);
    cudaGetSymbolAddress((void**)&Y,   d_Y);
    cudaGetSymbolAddress((void**)&Z,   d_Z);
    cudaGetSymbolAddress((void**)&p_feath, feat_h); cudaGetSymbolAddress((void**)&p_featl, feat_l);
    cudaGetSymbolAddress((void**)&p_embh,  emb_h);  cudaGetSymbolAddress((void**)&p_embl,  emb_l);
    cudaGetSymbolAddress((void**)&p_wnh,   wn_h);   cudaGetSymbolAddress((void**)&p_wnl,   wn_l);
    cudaGetSymbolAddress((void**)&p_kwth,  kwt_h);  cudaGetSymbolAddress((void**)&p_kwtl,  kwt_l);
    cudaGetSymbolAddress((void**)&p_qwth,  qwt_h);  cudaGetSymbolAddress((void**)&p_qwtl,  qwt_l);
    cudaGetSymbolAddress((void**)&p_vwth,  vwt_h);  cudaGetSymbolAddress((void**)&p_vwtl,  vwt_l);
    cudaGetSymbolAddress((void**)&p_mh,    m_h);    cudaGetSymbolAddress((void**)&p_ml,    m_l);
    cudaGetSymbolAddress((void**)&p_mth,   mt_h);   cudaGetSymbolAddress((void**)&p_mtl,   mt_l);
    cudaGetSymbolAddress((void**)&p_fwh,   fw_h);   cudaGetSymbolAddress((void**)&p_fwl,   fw_l);
    cudaGetSymbolAddress((void**)&p_fcwh,  fcw_h);  cudaGetSymbolAddress((void**)&p_fcwl,  fcw_l);
    cudaGetSymbolAddress((void**)&p_pth,   pt_h);
    cudaGetSymbolAddress((void**)&p_gh,    g_h);
    cudaGetSymbolAddress((void**)&p_hh,    h_h);

    cudaFuncSetAttribute((const void*)tc_gemm<4, 1>,  cudaFuncAttributeMaxDynamicSharedMemorySize, SMEM_BYTES);
    cudaFuncSetAttribute((const void*)tc_gemm<4, 3>,  cudaFuncAttributeMaxDynamicSharedMemorySize, SMEM_BYTES);
    cudaFuncSetAttribute((const void*)tc_gemm<12, 3>, cudaFuncAttributeMaxDynamicSharedMemorySize, SMEM_BYTES);
    cudaFuncSetAttribute((const void*)tc_gemm<24, 1>, cudaFuncAttributeMaxDynamicSharedMemorySize, SMEM_BYTES);
    cudaFuncSetAttribute((const void*)tc_gemm<27, 1>, cudaFuncAttributeMaxDynamicSharedMemorySize, SMEM_BYTES);
    cudaFuncSetAttribute((const void*)tc_gemm<5, 1>,  cudaFuncAttributeMaxDynamicSharedMemorySize, SMEM_BYTES);

    cudaStream_t s1 = g_ctx.s1, s2 = g_ctx.s2;
    dim3 tb(32, 8);
    dim3 tg(DIM / 32, DIM / 32);

    // ---- default stream prefix ----
    split_pad_kernel<<<(BATCH * DIM / 4 + 255) / 256, 256>>>(feat, p_feath, p_featl, BATCH * DIM, BATCH * DIM);
    embed_norm_kernel<<<NPAD, 256>>>(emb);
    split_pad_kernel<<<(NPAD * DIM / 4 + 255) / 256, 256>>>(emb, p_embh, p_embl, NEMB * DIM, NPAD * DIM);
    cudaEventRecord(g_ctx.eFork, 0);

    // ---- s1: M chain -> Y -> diag ----
    cudaStreamWaitEvent(s1, g_ctx.eFork, 0);
    transpose_bf_kernel<<<tg, tb, 0, s1>>>(Kw, p_kwth, p_kwtl);
    transpose_bf_kernel<<<tg, tb, 0, s1>>>(Qw, p_qwth, p_qwtl);
    tc_gemm<12, 3><<<dim3(DIM / BN, DIM / BM), 256, SMEM_BYTES, s1>>>(
        p_kwth, p_kwtl, p_qwth, p_qwtl, nullptr, Mm, p_mh, p_ml,
        DIM, DIM, DIM, DIM, DIM, DIM);
    cudaEventRecord(g_ctx.eM, s1);
    transpose_bf_kernel<<<tg, tb, 0, s1>>>(Mm, p_mth, p_mtl);
    tc_gemm<4, 3><<<dim3(DIM / BN, NPAD / BM), 256, SMEM_BYTES, s1>>>(
        p_embh, p_embl, p_mth, p_mtl, nullptr, Y, nullptr, nullptr,
        NEMB, DIM, DIM, DIM, DIM, DIM);
    diag_kernel<<<NEMB, 256, 0, s1>>>(emb);
    cudaEventRecord(g_ctx.e1, s1);

    // ---- s2: Vw/fw/fcw prep -> Z -> PT (1-product, hi-plane only) ----
    cudaStreamWaitEvent(s2, g_ctx.eFork, 0);
    transpose_bf_kernel<<<tg, tb, 0, s2>>>(Vw, p_vwth, p_vwtl);
    split_pad_kernel<<<(DIM * 2 * DIM / 4 + 255) / 256, 256, 0, s2>>>(fw, p_fwh, p_fwl, DIM * 2 * DIM, DIM * 2 * DIM);
    split_pad_kernel<<<(NPAD * DIM / 4 + 255) / 256, 256, 0, s2>>>(fcw, p_fcwh, p_fcwl, NCLS * DIM, NPAD * DIM);
    cudaStreamWaitEvent(s2, g_ctx.eM, 0);
    tc_gemm<4, 3><<<dim3(DIM / BN, NPAD / BM), 256, SMEM_BYTES, s2>>>(
        p_embh, p_embl, p_mh, p_ml, nullptr, Z, nullptr, nullptr,
        NEMB, DIM, DIM, DIM, DIM, DIM);
    tc_gemm<24, 1><<<dim3(DIM / BN, DIM / BM), 256, SMEM_BYTES, s2>>>(
        p_fwh,       nullptr, p_vwth, nullptr, nullptr, nullptr, p_pth,       nullptr,
        DIM, DIM, DIM, 2 * DIM, DIM, 2 * DIM);
    tc_gemm<24, 1><<<dim3(DIM / BN, DIM / BM), 256, SMEM_BYTES, s2>>>(
        p_fwh + DIM, nullptr, p_vwth, nullptr, nullptr, nullptr, p_pth + DIM, nullptr,
        DIM, DIM, DIM, 2 * DIM, DIM, 2 * DIM);
    cudaEventRecord(g_ctx.e2, s2);

    // ---- default stream: S chain (1-product) -> W ----
    feat_norm_kernel<<<BATCH, 256>>>(feat);
    tc_gemm<4, 1><<<dim3(NPAD / BN, BATCH / BM), 256, SMEM_BYTES>>>(
        p_feath, nullptr, p_wnh, nullptr, nullptr, S, nullptr, nullptr,
        BATCH, NEMB, DIM, DIM, DIM, NEMB);
    argmin_kernel<<<BATCH, 256>>>();
    refine_gather_kernel<<<BATCH, 256>>>(emb, feat, outq, outi);
    cudaStreamWaitEvent(0, g_ctx.eM, 0);
    tc_gemm<4, 3><<<dim3(DIM / BN, BATCH / BM), 256, SMEM_BYTES>>>(
        p_feath, p_featl, p_mh, p_ml, nullptr, W, nullptr, nullptr,
        BATCH, DIM, DIM, DIM, DIM, DIM);

    // ---- join, then tail chain (1-product H and pred) ----
    cudaStreamWaitEvent(0, g_ctx.e1, 0);
    cudaStreamWaitEvent(0, g_ctx.e2, 0);
    attn_mix2_kernel<<<BATCH, 256>>>(feat, outq);
    tc_gemm<27, 1><<<dim3(DIM / BN, BATCH / BM), 256, SMEM_BYTES>>>(
        p_gh, nullptr, p_pth, nullptr, fb, nullptr, p_hh, nullptr,
        BATCH, DIM, 2 * DIM, 2 * DIM, 2 * DIM, DIM);
    tc_gemm<5, 1><<<dim3(NPAD / BN, BATCH / BM), 256, SMEM_BYTES>>>(
        p_hh, nullptr, p_fcwh, nullptr, fcb, outp, nullptr, nullptr,
        BATCH, NCLS, DIM, DIM, DIM, NCLS);
}

// round 11
// speedup vs baseline: 1.4137x; 1.0353x over previous
#include <cuda_runtime.h>
#include <cuda_fp16.h>
#include <math.h>
#include <stdint.h>

#define BATCH 8192
#define DIM   2048
#define NEMB  1000
#define NCLS  1000
#define NPAD  1024

typedef __half f16;

// ---------------- fp32 scratch ----------------
__device__ float d_wn[NEMB * DIM];
__device__ float d_c[NEMB];
__device__ float d_rinv[BATCH];
__device__ float d_M[DIM * DIM];
__device__ float d_Y[NEMB * DIM];
__device__ float d_Z[NEMB * DIM];
__device__ float d_diag[NEMB];
__device__ int   d_bidx[BATCH];
__device__ float d_gap[BATCH];
// argmin partials from S epilogue: 32 slots (8 col-CTAs x 4 n-warps)
__device__ float d_pmin[32 * BATCH];
__device__ float d_psec[32 * BATCH];
__device__ int   d_pidx[32 * BATCH];
// s11 dot partials from W epilogue: 64 slots (16 col-CTAs x 4 n-warps)
__device__ float d_s11p[64 * BATCH];

// ---------------- fp16 hi/lo planes ----------------
__device__ f16 feat_h[BATCH * DIM],  feat_l[BATCH * DIM];
__device__ f16 emb_h[NPAD * DIM],    emb_l[NPAD * DIM];
__device__ f16 wn_h[NPAD * DIM];
__device__ f16 kwt_h[DIM * DIM],     kwt_l[DIM * DIM];
__device__ f16 qwt_h[DIM * DIM],     qwt_l[DIM * DIM];
__device__ f16 vwt_h[DIM * DIM];
__device__ f16 m_h[DIM * DIM],       m_l[DIM * DIM];
__device__ f16 mt_h[DIM * DIM],      mt_l[DIM * DIM];
__device__ f16 fw_h[DIM * 2 * DIM];
__device__ f16 fcw_h[NPAD * DIM];
__device__ f16 pt_h[DIM * 2 * DIM];
__device__ f16 g_h[BATCH * 2 * DIM];
__device__ f16 h_h[BATCH * DIM];

// ---------------- streams/events ----------------
namespace {
struct Ctx {
    cudaStream_t s1, s2;
    cudaEvent_t eFork, eM, e1, e2;
    Ctx() {
        cudaStreamCreateWithFlags(&s1, cudaStreamNonBlocking);
        cudaStreamCreateWithFlags(&s2, cudaStreamNonBlocking);
        cudaEventCreateWithFlags(&eFork, cudaEventDisableTiming);
        cudaEventCreateWithFlags(&eM,    cudaEventDisableTiming);
        cudaEventCreateWithFlags(&e1,    cudaEventDisableTiming);
        cudaEventCreateWithFlags(&e2,    cudaEventDisableTiming);
    }
};
Ctx g_ctx;
}

// ---------------- helpers ----------------
__device__ __forceinline__ uint32_t smem_to_u32(const void* p) {
    uint32_t a;
    asm("{ .reg .u64 t; cvta.to.shared.u64 t, %1; cvt.u32.u64 %0, t; }" : "=r"(a) : "l"(p));
    return a;
}
__device__ __forceinline__ void split1(float v, f16& h, f16& l) {
    h = __float2half_rn(v);
    l = __float2half_rn(v - __half2float(h));
}
__device__ __forceinline__ void ldsm4(uint32_t* r, uint32_t addr) {
    asm volatile("ldmatrix.sync.aligned.m8n8.x4.shared.b16 {%0,%1,%2,%3}, [%4];"
        : "=r"(r[0]), "=r"(r[1]), "=r"(r[2]), "=r"(r[3]) : "r"(addr));
}
__device__ __forceinline__ void ldsm2(uint32_t* r, uint32_t addr) {
    asm volatile("ldmatrix.sync.aligned.m8n8.x2.shared.b16 {%0,%1}, [%2];"
        : "=r"(r[0]), "=r"(r[1]) : "r"(addr));
}
__device__ __forceinline__ void mma16816(float* d, const uint32_t* a, const uint32_t* b) {
    asm volatile("mma.sync.aligned.m16n8k16.row.col.f32.f16.f16.f32 "
        "{%0,%1,%2,%3},{%4,%5,%6,%7},{%8,%9},{%0,%1,%2,%3};"
        : "+f"(d[0]), "+f"(d[1]), "+f"(d[2]), "+f"(d[3])
        : "r"(a[0]), "r"(a[1]), "r"(a[2]), "r"(a[3]), "r"(b[0]), "r"(b[1]));
}
__device__ __forceinline__ void cpa16(uint32_t dst, const void* src) {
    asm volatile("cp.async.cg.shared.global [%0], [%1], 16;" :: "r"(dst), "l"(src));
}
#define CP_COMMIT() asm volatile("cp.async.commit_group;" ::: "memory")
#define CP_WAIT(n)  asm volatile("cp.async.wait_group %0;" :: "n"(n) : "memory")

// ================= tensor-core GEMM (pre-split fp16, NT, f32 acc) =================
// NPROD=1: Ah*Bh. NPROD=2: + Ah*Bl. NPROD=3: + Al*Bh.
// EPI bits: 1=bias, 2=relu, 4=write f32, 8=write f16 hi plane,
//           32=fused row-dot with aux -> d_s11p, 64=fused argmin -> d_pmin/psec/pidx
#define BM 128
#define BN 128
#define STAGE_BYTES 32768
#define SMEM_BYTES  (2 * STAGE_BYTES)

template<int EPI, int NPROD>
__global__ __launch_bounds__(256, 2)
void tc_gemm(const f16* __restrict__ Ah, const f16* __restrict__ Al,
             const f16* __restrict__ Bh, const f16* __restrict__ Bl,
             const float* __restrict__ bias, const float* __restrict__ aux,
             float* __restrict__ Cf, f16* __restrict__ Ch,
             int M, int N, int K, int lda, int ldb, int ldc)
{
    extern __shared__ char smem[];
    const int tid  = threadIdx.x;
    const int lane = tid & 31;
    const int wid  = tid >> 5;
    const int wm   = (wid >> 2) << 6;
    const int wn   = (wid & 3) << 5;
    const int bm   = blockIdx.y * BM;
    const int bn   = blockIdx.x * BN;
    const uint32_t sb = smem_to_u32(smem);

    float acc[4][4][4];
    #pragma unroll
    for (int i = 0; i < 4; i++)
        #pragma unroll
        for (int j = 0; j < 4; j++)
            #pragma unroll
            for (int k = 0; k < 4; k++) acc[i][j][k] = 0.f;

    auto copy = [&](int s, int k0) {
        uint32_t base = sb + s * STAGE_BYTES;
        #pragma unroll
        for (int i = 0; i < 4; i++) {
            int id = (i << 8) + tid;
            int row = id >> 3, rem = id & 7, pl = rem >> 2, u = rem & 3;
            if (NPROD == 3 || pl == 0) {
                const f16* src = (pl ? Al : Ah) + (size_t)(bm + row) * lda + k0 + (u << 3);
                uint32_t dst = base + row * 128 + ((((u ^ (row & 7))) ^ (pl << 2)) << 4);
                cpa16(dst, src);
            }
        }
        #pragma unroll
        for (int i = 0; i < 4; i++) {
            int id = (i << 8) + tid;
            int row = id >> 3, rem = id & 7, pl = rem >> 2, u = rem & 3;
            if (NPROD >= 2 || pl == 0) {
                const f16* src = (pl ? Bl : Bh) + (size_t)(bn + row) * ldb + k0 + (u << 3);
                uint32_t dst = base + 16384 + row * 128 + ((((u ^ (row & 7))) ^ (pl << 2)) << 4);
                cpa16(dst, src);
            }
        }
    };

    copy(0, 0);
    CP_COMMIT();

    const int nc = K >> 5;
    for (int c = 0; c < nc; c++) {
        int s = c & 1;
        if (c + 1 < nc) {
            copy(s ^ 1, (c + 1) << 5);
            CP_COMMIT();
            CP_WAIT(1);
        } else {
            CP_WAIT(0);
        }
        __syncthreads();

        uint32_t a_s = sb + s * STAGE_BYTES;
        uint32_t b_s = a_s + 16384;
        #pragma unroll
        for (int h = 0; h < 2; h++) {
            uint32_t bhf[4][2], blf[4][2];
            #pragma unroll
            for (int nt = 0; nt < 4; nt++) {
                int r = wn + (nt << 3) + (lane & 7);
                int lu = (h << 1) + ((lane >> 3) & 1);
                uint32_t ad = b_s + r * 128 + ((uint32_t)(lu ^ (r & 7)) << 4);
                ldsm2(bhf[nt], ad);
                if (NPROD >= 2) ldsm2(blf[nt], ad ^ 64u);
            }
            #pragma unroll
            for (int mt = 0; mt < 4; mt++) {
                int g = lane >> 3;
                int r = wm + (mt << 4) + ((g & 1) << 3) + (lane & 7);
                int lu = (h << 1) + (g >> 1);
                uint32_t ad = a_s + r * 128 + ((uint32_t)(lu ^ (r & 7)) << 4);
                uint32_t af[4];
                ldsm4(af, ad);                       // A hi
                #pragma unroll
                for (int nt = 0; nt < 4; nt++) mma16816(acc[mt][nt], af, bhf[nt]);
                if (NPROD >= 2) {
                    #pragma unroll
                    for (int nt = 0; nt < 4; nt++) mma16816(acc[mt][nt], af, blf[nt]);
                }
                if (NPROD == 3) {
                    ldsm4(af, ad ^ 64u);             // A lo
                    #pragma unroll
                    for (int nt = 0; nt < 4; nt++) mma16816(acc[mt][nt], af, bhf[nt]);
                }
            }
        }
        __syncthreads();
    }

    // ---------------- epilogue ----------------
    #pragma unroll
    for (int mt = 0; mt < 4; mt++) {
        #pragma unroll
        for (int half = 0; half < 2; half++) {
            int rr = bm + wm + (mt << 4) + (lane >> 2) + half * 8;
            if (rr >= M) continue;

            if (EPI & 64) {
                // fused argmin over this tile's columns: v = c[n] - 2*rinv*S
                float rv = d_rinv[rr];
                float bmv = INFINITY, bsv = INFINITY;
                int biv = 0x7fffffff;
                #pragma unroll
                for (int nt = 0; nt < 4; nt++) {
                    #pragma unroll
                    for (int q = 0; q < 2; q++) {
                        int cn = bn + wn + (nt << 3) + ((lane & 3) << 1) + q;
                        float v = acc[mt][nt][half * 2 + q];
                        float val = (cn < N) ? (d_c[cn] - 2.0f * rv * v) : INFINITY;
                        if (val < bmv) { bsv = bmv; bmv = val; biv = cn; }
                        else if (val < bsv) bsv = val;
                    }
                }
                #pragma unroll
                for (int o = 1; o <= 2; o <<= 1) {
                    float om = __shfl_xor_sync(0xffffffffu, bmv, o);
                    float os = __shfl_xor_sync(0xffffffffu, bsv, o);
                    int   oi = __shfl_xor_sync(0xffffffffu, biv, o);
                    float nm = fminf(bmv, om);
                    float ns = fminf(fmaxf(bmv, om), fminf(bsv, os));
                    int ni = (om < bmv) ? oi : ((bmv < om) ? biv : min(biv, oi));
                    bmv = nm; bsv = ns; biv = ni;
                }
                if ((lane & 3) == 0) {
                    int slot = blockIdx.x * 4 + (wid & 3);
                    d_pmin[(size_t)slot * BATCH + rr] = bmv;
                    d_psec[(size_t)slot * BATCH + rr] = bsv;
                    d_pidx[(size_t)slot * BATCH + rr] = biv;
                }
                continue;
            }

            if (EPI & 32) {
                // fused row-dot: partial sum of C[rr,:] * aux[rr,:]
                float dsum = 0.f;
                #pragma unroll
                for (int nt = 0; nt < 4; nt++) {
                    #pragma unroll
                    for (int q = 0; q < 2; q++) {
                        int cn = bn + wn + (nt << 3) + ((lane & 3) << 1) + q;
                        dsum += acc[mt][nt][half * 2 + q] * aux[(size_t)rr * ldc + cn];
                    }
                }
                dsum += __shfl_xor_sync(0xffffffffu, dsum, 1);
                dsum += __shfl_xor_sync(0xffffffffu, dsum, 2);
                if ((lane & 3) == 0) {
                    int slot = blockIdx.x * 4 + (wid & 3);
                    d_s11p[(size_t)slot * BATCH + rr] = dsum;
                }
                continue;
            }

            #pragma unroll
            for (int nt = 0; nt < 4; nt++) {
                int cn = bn + wn + (nt << 3) + ((lane & 3) << 1);
                float v0 = acc[mt][nt][half * 2 + 0];
                float v1 = acc[mt][nt][half * 2 + 1];
                if (EPI & 1) {
                    if (cn < N)     v0 += bias[cn];
                    if (cn + 1 < N) v1 += bias[cn + 1];
                }
                if (EPI & 2) { v0 = fmaxf(v0, 0.f); v1 = fmaxf(v1, 0.f); }
                if (EPI & 4) {
                    if (cn < N)     Cf[(size_t)rr * ldc + cn] = v0;
                    if (cn + 1 < N) Cf[(size_t)rr * ldc + cn + 1] = v1;
                }
                if (EPI & 8) {
                    if (cn + 1 < N) {
                        f16 h0 = __float2half_rn(v0);
                        f16 h1 = __float2half_rn(v1);
                        uint32_t hp = (uint32_t)__half_as_ushort(h0) | ((uint32_t)__half_as_ushort(h1) << 16);
                        *(uint32_t*)(Ch + (size_t)rr * ldc + cn) = hp;
                    } else if (cn < N) {
                        Ch[(size_t)rr * ldc + cn] = __float2half_rn(v0);
                    }
                }
            }
        }
    }
}

// ================= small kernels =================
__device__ __forceinline__ float warpReduceSum(float v) {
    #pragma unroll
    for (int o = 16; o > 0; o >>= 1) v += __shfl_down_sync(0xffffffffu, v, o);
    return v;
}
__device__ __forceinline__ float blockReduceSum(float v, float* smem) {
    __syncthreads();
    int lane = threadIdx.x & 31, wid = threadIdx.x >> 5;
    v = warpReduceSum(v);
    if (lane == 0) smem[wid] = v;
    __syncthreads();
    int nw = blockDim.x >> 5;
    float t = (threadIdx.x < nw) ? smem[threadIdx.x] : 0.0f;
    if (wid == 0) { t = warpReduceSum(t); if (lane == 0) smem[0] = t; }
    __syncthreads();
    return smem[0];
}

// pack 4 floats -> hi/lo uint2 pairs
__device__ __forceinline__ void pack4(float4 v, uint2& hp, uint2& lp) {
    f16 h0, l0, h1, l1, h2, l2, h3, l3;
    split1(v.x, h0, l0); split1(v.y, h1, l1);
    split1(v.z, h2, l2); split1(v.w, h3, l3);
    hp = make_uint2(
        (uint32_t)__half_as_ushort(h0) | ((uint32_t)__half_as_ushort(h1) << 16),
        (uint32_t)__half_as_ushort(h2) | ((uint32_t)__half_as_ushort(h3) << 16));
    lp = make_uint2(
        (uint32_t)__half_as_ushort(l0) | ((uint32_t)__half_as_ushort(l1) << 16),
        (uint32_t)__half_as_ushort(l2) | ((uint32_t)__half_as_ushort(l3) << 16));
}

// fused: feat row norm + hi/lo split (single read of feat)
__global__ __launch_bounds__(256) void feat_prep_kernel(const float* __restrict__ feat) {
    int b = blockIdx.x, tid = threadIdx.x;
    const float4* row = (const float4*)(feat + (size_t)b * DIM);
    float4 v0 = row[tid];
    float4 v1 = row[tid + 256];
    float s = v0.x * v0.x + v0.y * v0.y + v0.z * v0.z + v0.w * v0.w
            + v1.x * v1.x + v1.y * v1.y + v1.z * v1.z + v1.w * v1.w;
    __shared__ float red[32];
    s = blockReduceSum(s, red);
    if (tid == 0) d_rinv[b] = 1.0f / fmaxf(sqrtf(s), 1e-12f);
    uint2 hp, lp;
    size_t o = (size_t)b * DIM;
    pack4(v0, hp, lp);
    *(uint2*)(feat_h + o + tid * 4) = hp;
    *(uint2*)(feat_l + o + tid * 4) = lp;
    pack4(v1, hp, lp);
    *(uint2*)(feat_h + o + (tid + 256) * 4) = hp;
    *(uint2*)(feat_l + o + (tid + 256) * 4) = lp;
}

__global__ __launch_bounds__(256) void transpose_bf_kernel(
    const float* __restrict__ in, f16* __restrict__ oh, f16* __restrict__ ol)
{
    __shared__ float t[32][33];
    int bx = blockIdx.x * 32, by = blockIdx.y * 32;
    #pragma unroll
    for (int j = threadIdx.y; j < 32; j += 8)
        t[j][threadIdx.x] = in[(size_t)(by + j) * DIM + bx + threadIdx.x];
    __syncthreads();
    #pragma unroll
    for (int j = threadIdx.y; j < 32; j += 8) {
        float v = t[threadIdx.x][j];
        f16 h, l;
        split1(v, h, l);
        size_t o = (size_t)(bx + j) * DIM + by + threadIdx.x;
        oh[o] = h;
        if (ol) ol[o] = l;
    }
}

__global__ __launch_bounds__(256) void split_pad_kernel(
    const float* __restrict__ src, f16* __restrict__ dh, f16* __restrict__ dl,
    int valid, int total)
{
    int i = (blockIdx.x * 256 + threadIdx.x) * 4;
    if (i >= total) return;
    float4 v;
    if (i + 3 < valid) v = *(const float4*)(src + i);
    else {
        v.x = (i + 0 < valid) ? src[i + 0] : 0.f;
        v.y = (i + 1 < valid) ? src[i + 1] : 0.f;
        v.z = (i + 2 < valid) ? src[i + 2] : 0.f;
        v.w = (i + 3 < valid) ? src[i + 3] : 0.f;
    }
    uint2 hp, lp;
    pack4(v, hp, lp);
    *(uint2*)(dh + i) = hp;
    if (dl) *(uint2*)(dl + i) = lp;
}

__global__ __launch_bounds__(256) void embed_norm_kernel(const float* __restrict__ emb) {
    int n = blockIdx.x, tid = threadIdx.x;
    if (n >= NEMB) {
        f16 z = __float2half_rn(0.f);
        for (int j = tid; j < DIM; j += 256) wn_h[(size_t)n * DIM + j] = z;
        return;
    }
    const float* row = emb + (size_t)n * DIM;
    float s = 0.0f;
    for (int j = tid; j < DIM; j += 256) { float v = row[j]; s = fmaf(v, v, s); }
    __shared__ float red[32];
    s = blockReduceSum(s, red);
    float inv = 1.0f / fmaxf(sqrtf(s), 1e-12f);
    float c = 0.0f;
    for (int j = tid; j < DIM; j += 256) {
        float v = row[j] * inv;
        d_wn[(size_t)n * DIM + j] = v;
        wn_h[(size_t)n * DIM + j] = __float2half_rn(v);
        c = fmaf(v, v, c);
    }
    c = blockReduceSum(c, red);
    if (tid == 0) d_c[n] = c;
}

// merge 32 argmin partials per row
__global__ __launch_bounds__(256) void argmin_combine_kernel() {
    int b = blockIdx.x * 256 + threadIdx.x;
    float m = INFINITY, s = INFINITY;
    int i = 0x7fffffff;
    #pragma unroll 4
    for (int p = 0; p < 32; p++) {
        float pm = d_pmin[(size_t)p * BATCH + b];
        float ps = d_psec[(size_t)p * BATCH + b];
        int   pi = d_pidx[(size_t)p * BATCH + b];
        float nm = fminf(m, pm);
        float ns = fminf(fmaxf(m, pm), fminf(s, ps));
        int ni = (pm < m) ? pi : ((m < pm) ? i : min(i, pi));
        m = nm; s = ns; i = ni;
    }
    d_bidx[b] = i;
    d_gap[b] = s - m;
}

__global__ __launch_bounds__(256) void refine_gather_kernel(
    const float* __restrict__ emb, const float* __restrict__ feat,
    float* __restrict__ outq, float* __restrict__ outi)
{
    int b = blockIdx.x, tid = threadIdx.x;
    int idx = d_bidx[b];
    if (d_gap[b] < 1e-3f) {
        __shared__ float sf[DIM];
        const float* f = feat + (size_t)b * DIM;
        for (int j = tid; j < DIM; j += 256) sf[j] = f[j];
        __syncthreads();
        float r = d_rinv[b];
        int wid = tid >> 5, lane = tid & 31;
        float best = INFINITY; int bi = 0x7fffffff;
        for (int n = wid; n < NEMB; n += 8) {
            const float* w = d_wn + (size_t)n * DIM;
            float s = 0.0f;
            for (int j = lane; j < DIM; j += 32) s = fmaf(sf[j], w[j], s);
            s = warpReduceSum(s);
            s = __shfl_sync(0xffffffffu, s, 0);
            float v = d_c[n] - 2.0f * r * s;
            if (v < best) { best = v; bi = n; }
        }
        __shared__ float wb[8]; __shared__ int wi[8];
        if (lane == 0) { wb[wid] = best; wi[wid] = bi; }
        __syncthreads();
        if (tid == 0) {
            float bb = wb[0]; int ii = wi[0];
            for (int w = 1; w < 8; w++)
                if (wb[w] < bb || (wb[w] == bb && wi[w] < ii)) { bb = wb[w]; ii = wi[w]; }
            wi[0] = ii;
        }
        __syncthreads();
        idx = wi[0];
        if (tid == 0) d_bidx[b] = idx;
    }
    const float* src = emb + (size_t)idx * DIM;
    float* dst = outq + (size_t)b * DIM;
    for (int j = tid; j < DIM; j += 256) dst[j] = src[j];
    if (tid == 0) outi[b] = (float)idx;
}

__global__ __launch_bounds__(256) void diag_kernel(const float* __restrict__ emb) {
    int n = blockIdx.x, tid = threadIdx.x;
    const float* y = d_Y + (size_t)n * DIM;
    const float* e = emb + (size_t)n * DIM;
    float s = 0.0f;
    for (int j = tid; j < DIM; j += 256) s = fmaf(y[j], e[j], s);
    __shared__ float red[32];
    s = blockReduceSum(s, red);
    if (tid == 0) d_diag[n] = s;
}

// scores -> softmax -> mix; s11 comes from d_s11p partials (W epilogue fusion)
__global__ __launch_bounds__(256) void attn_mix2_kernel(
    const float* __restrict__ feat, const float* __restrict__ outq)
{
    int b = blockIdx.x, tid = threadIdx.x;
    int idx = d_bidx[b];
    const float* t1 = feat + (size_t)b * DIM;
    const float* t0 = outq + (size_t)b * DIM;
    const float* yr = d_Y + (size_t)idx * DIM;
    const float* zr = d_Z + (size_t)idx * DIM;
    float s01 = 0, s10 = 0, s11 = 0;
    for (int j = tid; j < DIM; j += 256) {
        float f = t1[j];
        s01 = fmaf(yr[j], f, s01);
        s10 = fmaf(zr[j], f, s10);
    }
    if (tid < 64) s11 = d_s11p[(size_t)tid * BATCH + b];
    __shared__ float red[32];
    s01 = blockReduceSum(s01, red);
    s10 = blockReduceSum(s10, red);
    s11 = blockReduceSum(s11, red);
    float s00 = d_diag[idx];
    float m0 = fmaxf(s00, s10);
    float e00 = expf(s00 - m0), e10 = expf(s10 - m0);
    float iv0 = 1.0f / (e00 + e10);
    float a00 = e00 * iv0, a10 = e10 * iv0;
    float m1 = fmaxf(s01, s11);
    float e01 = expf(s01 - m1), e11 = expf(s11 - m1);
    float iv1 = 1.0f / (e01 + e11);
    float a01 = e01 * iv1, a11 = e11 * iv1;
    size_t go = (size_t)b * 2 * DIM;
    for (int j = tid; j < DIM; j += 256) {
        float v0 = t0[j], v1 = t1[j];
        g_h[go + j]       = __float2half_rn(fmaf(a00, v0, a10 * v1));
        g_h[go + DIM + j] = __float2half_rn(fmaf(a01, v0, a11 * v1));
    }
}

// ================= launch =================
extern "C" void kernel_launch(void* const* d_in, const int* in_sizes, int n_in,
                              void* d_out, int out_size)
{
    const float* feat = (const float*)d_in[0];
    const float* emb  = (const float*)d_in[1];
    const float* Kw   = (const float*)d_in[2];
    const float* Qw   = (const float*)d_in[3];
    const float* Vw   = (const float*)d_in[4];
    const float* fw   = (const float*)d_in[5];
    const float* fb   = (const float*)d_in[6];
    const float* fcw  = (const float*)d_in[7];
    const float* fcb  = (const float*)d_in[8];

    float* out  = (float*)d_out;
    float* outq = out;
    float* outp = out + (size_t)BATCH * DIM;
    float* outi = outp + (size_t)BATCH * NCLS;

    float *Mm, *Y, *Z;
    f16 *p_feath, *p_featl, *p_embh, *p_embl, *p_wnh;
    f16 *p_kwth, *p_kwtl, *p_qwth, *p_qwtl, *p_vwth;
    f16 *p_mh, *p_ml, *p_mth, *p_mtl, *p_fwh, *p_fcwh;
    f16 *p_pth, *p_gh, *p_hh;
    cudaGetSymbolAddress((void**)&Mm,  d_M);
    cudaGetSymbolAddress((void**)&Y,   d_Y);
    cudaGetSymbolAddress((void**)&Z,   d_Z);
    cudaGetSymbolAddress((void**)&p_feath, feat_h); cudaGetSymbolAddress((void**)&p_featl, feat_l);
    cudaGetSymbolAddress((void**)&p_embh,  emb_h);  cudaGetSymbolAddress((void**)&p_embl,  emb_l);
    cudaGetSymbolAddress((void**)&p_wnh,   wn_h);
    cudaGetSymbolAddress((void**)&p_kwth,  kwt_h);  cudaGetSymbolAddress((void**)&p_kwtl,  kwt_l);
    cudaGetSymbolAddress((void**)&p_qwth,  qwt_h);  cudaGetSymbolAddress((void**)&p_qwtl,  qwt_l);
    cudaGetSymbolAddress((void**)&p_vwth,  vwt_h);
    cudaGetSymbolAddress((void**)&p_mh,    m_h);    cudaGetSymbolAddress((void**)&p_ml,    m_l);
    cudaGetSymbolAddress((void**)&p_mth,   mt_h);   cudaGetSymbolAddress((void**)&p_mtl,   mt_l);
    cudaGetSymbolAddress((void**)&p_fwh,   fw_h);
    cudaGetSymbolAddress((void**)&p_fcwh,  fcw_h);
    cudaGetSymbolAddress((void**)&p_pth,   pt_h);
    cudaGetSymbolAddress((void**)&p_gh,    g_h);
    cudaGetSymbolAddress((void**)&p_hh,    h_h);

    cudaFuncSetAttribute((const void*)tc_gemm<64, 1>, cudaFuncAttributeMaxDynamicSharedMemorySize, SMEM_BYTES);
    cudaFuncSetAttribute((const void*)tc_gemm<32, 3>, cudaFuncAttributeMaxDynamicSharedMemorySize, SMEM_BYTES);
    cudaFuncSetAttribute((const void*)tc_gemm<4, 3>,  cudaFuncAttributeMaxDynamicSharedMemorySize, SMEM_BYTES);
    cudaFuncSetAttribute((const void*)tc_gemm<12, 3>, cudaFuncAttributeMaxDynamicSharedMemorySize, SMEM_BYTES);
    cudaFuncSetAttribute((const void*)tc_gemm<8, 1>,  cudaFuncAttributeMaxDynamicSharedMemorySize, SMEM_BYTES);
    cudaFuncSetAttribute((const void*)tc_gemm<11, 1>, cudaFuncAttributeMaxDynamicSharedMemorySize, SMEM_BYTES);
    cudaFuncSetAttribute((const void*)tc_gemm<5, 1>,  cudaFuncAttributeMaxDynamicSharedMemorySize, SMEM_BYTES);

    cudaStream_t s1 = g_ctx.s1, s2 = g_ctx.s2;
    dim3 tb(32, 8);
    dim3 tg(DIM / 32, DIM / 32);

    // ---- default stream prefix ----
    feat_prep_kernel<<<BATCH, 256>>>(feat);
    embed_norm_kernel<<<NPAD, 256>>>(emb);
    split_pad_kernel<<<(NPAD * DIM / 4 + 255) / 256, 256>>>(emb, p_embh, p_embl, NEMB * DIM, NPAD * DIM);
    cudaEventRecord(g_ctx.eFork, 0);

    // ---- s1: M chain -> Y -> diag ----
    cudaStreamWaitEvent(s1, g_ctx.eFork, 0);
    transpose_bf_kernel<<<tg, tb, 0, s1>>>(Kw, p_kwth, p_kwtl);
    transpose_bf_kernel<<<tg, tb, 0, s1>>>(Qw, p_qwth, p_qwtl);
    tc_gemm<12, 3><<<dim3(DIM / BN, DIM / BM), 256, SMEM_BYTES, s1>>>(
        p_kwth, p_kwtl, p_qwth, p_qwtl, nullptr, nullptr, Mm, p_mh,
        DIM, DIM, DIM, DIM, DIM, DIM);
    cudaEventRecord(g_ctx.eM, s1);
    transpose_bf_kernel<<<tg, tb, 0, s1>>>(Mm, p_mth, p_mtl);
    tc_gemm<4, 3><<<dim3(DIM / BN, NPAD / BM), 256, SMEM_BYTES, s1>>>(
        p_embh, p_embl, p_mth, p_mtl, nullptr, nullptr, Y, nullptr,
        NEMB, DIM, DIM, DIM, DIM, DIM);
    diag_kernel<<<NEMB, 256, 0, s1>>>(emb);
    cudaEventRecord(g_ctx.e1, s1);

    // ---- s2: Vw/fw/fcw prep -> Z -> PT (1-product, hi-plane) ----
    cudaStreamWaitEvent(s2, g_ctx.eFork, 0);
    transpose_bf_kernel<<<tg, tb, 0, s2>>>(Vw, p_vwth, nullptr);
    split_pad_kernel<<<(DIM * 2 * DIM / 4 + 255) / 256, 256, 0, s2>>>(fw, p_fwh, nullptr, DIM * 2 * DIM, DIM * 2 * DIM);
    split_pad_kernel<<<(NPAD * DIM / 4 + 255) / 256, 256, 0, s2>>>(fcw, p_fcwh, nullptr, NCLS * DIM, NPAD * DIM);
    cudaStreamWaitEvent(s2, g_ctx.eM, 0);
    tc_gemm<4, 3><<<dim3(DIM / BN, NPAD / BM), 256, SMEM_BYTES, s2>>>(
        p_embh, p_embl, p_mh, p_ml, nullptr, nullptr, Z, nullptr,
        NEMB, DIM, DIM, DIM, DIM, DIM);
    tc_gemm<8, 1><<<dim3(DIM / BN, DIM / BM), 256, SMEM_BYTES, s2>>>(
        p_fwh,       nullptr, p_vwth, nullptr, nullptr, nullptr, nullptr, p_pth,
        DIM, DIM, DIM, 2 * DIM, DIM, 2 * DIM);
    tc_gemm<8, 1><<<dim3(DIM / BN, DIM / BM), 256, SMEM_BYTES, s2>>>(
        p_fwh + DIM, nullptr, p_vwth, nullptr, nullptr, nullptr, nullptr, p_pth + DIM,
        DIM, DIM, DIM, 2 * DIM, DIM, 2 * DIM);
    cudaEventRecord(g_ctx.e2, s2);

    // ---- default stream: S (fused argmin) -> combine -> refine -> W (fused s11 dot) ----
    tc_gemm<64, 1><<<dim3(NPAD / BN, BATCH / BM), 256, SMEM_BYTES>>>(
        p_feath, nullptr, p_wnh, nullptr, nullptr, nullptr, nullptr, nullptr,
        BATCH, NEMB, DIM, DIM, DIM, NEMB);
    argmin_combine_kernel<<<BATCH / 256, 256>>>();
    refine_gather_kernel<<<BATCH, 256>>>(emb, feat, outq, outi);
    cudaStreamWaitEvent(0, g_ctx.eM, 0);
    tc_gemm<32, 3><<<dim3(DIM / BN, BATCH / BM), 256, SMEM_BYTES>>>(
        p_feath, p_featl, p_mh, p_ml, nullptr, feat, nullptr, nullptr,
        BATCH, DIM, DIM, DIM, DIM, DIM);

    // ---- join, then tail chain ----
    cudaStreamWaitEvent(0, g_ctx.e1, 0);
    cudaStreamWaitEvent(0, g_ctx.e2, 0);
    attn_mix2_kernel<<<BATCH, 256>>>(feat, outq);
    tc_gemm<11, 1><<<dim3(DIM / BN, BATCH / BM), 256, SMEM_BYTES>>>(
        p_gh, nullptr, p_pth, nullptr, fb, nullptr, nullptr, p_hh,
        BATCH, DIM, 2 * DIM, 2 * DIM, 2 * DIM, DIM);
    tc_gemm<5, 1><<<dim3(NPAD / BN, BATCH / BM), 256, SMEM_BYTES>>>(
        p_hh, nullptr, p_fcwh, nullptr, fcb, nullptr, outp, nullptr,
        BATCH, NCLS, DIM, DIM, DIM, NCLS);
}

// round 12
// speedup vs baseline: 1.4593x; 1.0323x over previous
#include <cuda_runtime.h>
#include <cuda_fp16.h>
#include <math.h>
#include <stdint.h>

#define BATCH 8192
#define HALFB 4096
#define DIM   2048
#define NEMB  1000
#define NCLS  1000
#define NPAD  1024

typedef __half f16;

// ---------------- fp32 scratch ----------------
__device__ float d_wn[NEMB * DIM];
__device__ float d_c[NEMB];
__device__ float d_rinv[BATCH];
__device__ float d_M[DIM * DIM];
__device__ float d_Y[NEMB * DIM];
__device__ float d_Z[NEMB * DIM];
__device__ float d_diag[NEMB];
__device__ int   d_bidx[BATCH];
__device__ float d_gap[BATCH];
__device__ float d_pmin[32 * BATCH];
__device__ float d_psec[32 * BATCH];
__device__ int   d_pidx[32 * BATCH];
__device__ float d_s11p[64 * BATCH];

// ---------------- fp16 hi/lo planes ----------------
__device__ f16 feat_h[BATCH * DIM],  feat_l[BATCH * DIM];
__device__ f16 emb_h[NPAD * DIM],    emb_l[NPAD * DIM];
__device__ f16 wn_h[NPAD * DIM];
__device__ f16 kwt_h[DIM * DIM],     kwt_l[DIM * DIM];
__device__ f16 qwt_h[DIM * DIM],     qwt_l[DIM * DIM];
__device__ f16 vwt_h[DIM * DIM];
__device__ f16 m_h[DIM * DIM],       m_l[DIM * DIM];
__device__ f16 mt_h[DIM * DIM],      mt_l[DIM * DIM];
__device__ f16 fw_h[DIM * 2 * DIM];
__device__ f16 fcw_h[NPAD * DIM];
__device__ f16 pt_h[DIM * 2 * DIM];
__device__ f16 g_h[BATCH * 2 * DIM];
__device__ f16 h_h[BATCH * DIM];

// ---------------- streams/events ----------------
namespace {
struct Ctx {
    cudaStream_t s1, s2, s3;
    cudaEvent_t eFork, eM, e1, e2, eCmb, e3;
    Ctx() {
        cudaStreamCreateWithFlags(&s1, cudaStreamNonBlocking);
        cudaStreamCreateWithFlags(&s2, cudaStreamNonBlocking);
        cudaStreamCreateWithFlags(&s3, cudaStreamNonBlocking);
        cudaEventCreateWithFlags(&eFork, cudaEventDisableTiming);
        cudaEventCreateWithFlags(&eM,    cudaEventDisableTiming);
        cudaEventCreateWithFlags(&e1,    cudaEventDisableTiming);
        cudaEventCreateWithFlags(&e2,    cudaEventDisableTiming);
        cudaEventCreateWithFlags(&eCmb,  cudaEventDisableTiming);
        cudaEventCreateWithFlags(&e3,    cudaEventDisableTiming);
    }
};
Ctx g_ctx;
}

// ---------------- helpers ----------------
__device__ __forceinline__ uint32_t smem_to_u32(const void* p) {
    uint32_t a;
    asm("{ .reg .u64 t; cvta.to.shared.u64 t, %1; cvt.u32.u64 %0, t; }" : "=r"(a) : "l"(p));
    return a;
}
__device__ __forceinline__ void split1(float v, f16& h, f16& l) {
    h = __float2half_rn(v);
    l = __float2half_rn(v - __half2float(h));
}
__device__ __forceinline__ void ldsm4(uint32_t* r, uint32_t addr) {
    asm volatile("ldmatrix.sync.aligned.m8n8.x4.shared.b16 {%0,%1,%2,%3}, [%4];"
        : "=r"(r[0]), "=r"(r[1]), "=r"(r[2]), "=r"(r[3]) : "r"(addr));
}
__device__ __forceinline__ void ldsm2(uint32_t* r, uint32_t addr) {
    asm volatile("ldmatrix.sync.aligned.m8n8.x2.shared.b16 {%0,%1}, [%2];"
        : "=r"(r[0]), "=r"(r[1]) : "r"(addr));
}
__device__ __forceinline__ void mma16816(float* d, const uint32_t* a, const uint32_t* b) {
    asm volatile("mma.sync.aligned.m16n8k16.row.col.f32.f16.f16.f32 "
        "{%0,%1,%2,%3},{%4,%5,%6,%7},{%8,%9},{%0,%1,%2,%3};"
        : "+f"(d[0]), "+f"(d[1]), "+f"(d[2]), "+f"(d[3])
        : "r"(a[0]), "r"(a[1]), "r"(a[2]), "r"(a[3]), "r"(b[0]), "r"(b[1]));
}
__device__ __forceinline__ void cpa16(uint32_t dst, const void* src) {
    asm volatile("cp.async.cg.shared.global [%0], [%1], 16;" :: "r"(dst), "l"(src));
}
#define CP_COMMIT() asm volatile("cp.async.commit_group;" ::: "memory")
#define CP_WAIT(n)  asm volatile("cp.async.wait_group %0;" :: "n"(n) : "memory")

// ================= tensor-core GEMM (pre-split fp16, NT, f32 acc) =================
// NPROD=1: Ah*Bh. NPROD=2: + Ah*Bl. NPROD=3: + Al*Bh.
// EPI bits: 1=bias, 2=relu, 4=write f32, 8=write f16 hi plane, 16=also write lo plane,
//           32=fused row-dot with aux -> d_s11p, 64=fused argmin -> partials
#define BM 128
#define BN 128
#define STAGE_BYTES 32768
#define SMEM_BYTES  (2 * STAGE_BYTES)

template<int EPI, int NPROD>
__global__ __launch_bounds__(256, 2)
void tc_gemm(const f16* __restrict__ Ah, const f16* __restrict__ Al,
             const f16* __restrict__ Bh, const f16* __restrict__ Bl,
             const float* __restrict__ bias, const float* __restrict__ aux,
             float* __restrict__ Cf, f16* __restrict__ Ch, f16* __restrict__ Cl,
             int M, int N, int K, int lda, int ldb, int ldc, int prow0)
{
    extern __shared__ char smem[];
    const int tid  = threadIdx.x;
    const int lane = tid & 31;
    const int wid  = tid >> 5;
    const int wm   = (wid >> 2) << 6;
    const int wn   = (wid & 3) << 5;
    const int bm   = blockIdx.y * BM;
    const int bn   = blockIdx.x * BN;
    const uint32_t sb = smem_to_u32(smem);

    float acc[4][4][4];
    #pragma unroll
    for (int i = 0; i < 4; i++)
        #pragma unroll
        for (int j = 0; j < 4; j++)
            #pragma unroll
            for (int k = 0; k < 4; k++) acc[i][j][k] = 0.f;

    auto copy = [&](int s, int k0) {
        uint32_t base = sb + s * STAGE_BYTES;
        #pragma unroll
        for (int i = 0; i < 4; i++) {
            int id = (i << 8) + tid;
            int row = id >> 3, rem = id & 7, pl = rem >> 2, u = rem & 3;
            if (NPROD == 3 || pl == 0) {
                const f16* src = (pl ? Al : Ah) + (size_t)(bm + row) * lda + k0 + (u << 3);
                uint32_t dst = base + row * 128 + ((((u ^ (row & 7))) ^ (pl << 2)) << 4);
                cpa16(dst, src);
            }
        }
        #pragma unroll
        for (int i = 0; i < 4; i++) {
            int id = (i << 8) + tid;
            int row = id >> 3, rem = id & 7, pl = rem >> 2, u = rem & 3;
            if (NPROD >= 2 || pl == 0) {
                const f16* src = (pl ? Bl : Bh) + (size_t)(bn + row) * ldb + k0 + (u << 3);
                uint32_t dst = base + 16384 + row * 128 + ((((u ^ (row & 7))) ^ (pl << 2)) << 4);
                cpa16(dst, src);
            }
        }
    };

    copy(0, 0);
    CP_COMMIT();

    const int nc = K >> 5;
    for (int c = 0; c < nc; c++) {
        int s = c & 1;
        if (c + 1 < nc) {
            copy(s ^ 1, (c + 1) << 5);
            CP_COMMIT();
            CP_WAIT(1);
        } else {
            CP_WAIT(0);
        }
        __syncthreads();

        uint32_t a_s = sb + s * STAGE_BYTES;
        uint32_t b_s = a_s + 16384;
        #pragma unroll
        for (int h = 0; h < 2; h++) {
            uint32_t bhf[4][2], blf[4][2];
            #pragma unroll
            for (int nt = 0; nt < 4; nt++) {
                int r = wn + (nt << 3) + (lane & 7);
                int lu = (h << 1) + ((lane >> 3) & 1);
                uint32_t ad = b_s + r * 128 + ((uint32_t)(lu ^ (r & 7)) << 4);
                ldsm2(bhf[nt], ad);
                if (NPROD >= 2) ldsm2(blf[nt], ad ^ 64u);
            }
            #pragma unroll
            for (int mt = 0; mt < 4; mt++) {
                int g = lane >> 3;
                int r = wm + (mt << 4) + ((g & 1) << 3) + (lane & 7);
                int lu = (h << 1) + (g >> 1);
                uint32_t ad = a_s + r * 128 + ((uint32_t)(lu ^ (r & 7)) << 4);
                uint32_t af[4];
                ldsm4(af, ad);                       // A hi
                #pragma unroll
                for (int nt = 0; nt < 4; nt++) mma16816(acc[mt][nt], af, bhf[nt]);
                if (NPROD >= 2) {
                    #pragma unroll
                    for (int nt = 0; nt < 4; nt++) mma16816(acc[mt][nt], af, blf[nt]);
                }
                if (NPROD == 3) {
                    ldsm4(af, ad ^ 64u);             // A lo
                    #pragma unroll
                    for (int nt = 0; nt < 4; nt++) mma16816(acc[mt][nt], af, bhf[nt]);
                }
            }
        }
        __syncthreads();
    }

    // ---------------- epilogue ----------------
    #pragma unroll
    for (int mt = 0; mt < 4; mt++) {
        #pragma unroll
        for (int half = 0; half < 2; half++) {
            int rr = bm + wm + (mt << 4) + (lane >> 2) + half * 8;
            if (rr >= M) continue;

            if (EPI & 64) {
                float rv = d_rinv[prow0 + rr];
                float bmv = INFINITY, bsv = INFINITY;
                int biv = 0x7fffffff;
                #pragma unroll
                for (int nt = 0; nt < 4; nt++) {
                    #pragma unroll
                    for (int q = 0; q < 2; q++) {
                        int cn = bn + wn + (nt << 3) + ((lane & 3) << 1) + q;
                        float v = acc[mt][nt][half * 2 + q];
                        float val = (cn < N) ? (d_c[cn] - 2.0f * rv * v) : INFINITY;
                        if (val < bmv) { bsv = bmv; bmv = val; biv = cn; }
                        else if (val < bsv) bsv = val;
                    }
                }
                #pragma unroll
                for (int o = 1; o <= 2; o <<= 1) {
                    float om = __shfl_xor_sync(0xffffffffu, bmv, o);
                    float os = __shfl_xor_sync(0xffffffffu, bsv, o);
                    int   oi = __shfl_xor_sync(0xffffffffu, biv, o);
                    float nm = fminf(bmv, om);
                    float ns = fminf(fmaxf(bmv, om), fminf(bsv, os));
                    int ni = (om < bmv) ? oi : ((bmv < om) ? biv : min(biv, oi));
                    bmv = nm; bsv = ns; biv = ni;
                }
                if ((lane & 3) == 0) {
                    int slot = blockIdx.x * 4 + (wid & 3);
                    d_pmin[(size_t)slot * BATCH + prow0 + rr] = bmv;
                    d_psec[(size_t)slot * BATCH + prow0 + rr] = bsv;
                    d_pidx[(size_t)slot * BATCH + prow0 + rr] = biv;
                }
                continue;
            }

            if (EPI & 32) {
                float dsum = 0.f;
                #pragma unroll
                for (int nt = 0; nt < 4; nt++) {
                    #pragma unroll
                    for (int q = 0; q < 2; q++) {
                        int cn = bn + wn + (nt << 3) + ((lane & 3) << 1) + q;
                        dsum += acc[mt][nt][half * 2 + q] * aux[(size_t)rr * ldc + cn];
                    }
                }
                dsum += __shfl_xor_sync(0xffffffffu, dsum, 1);
                dsum += __shfl_xor_sync(0xffffffffu, dsum, 2);
                if ((lane & 3) == 0) {
                    int slot = blockIdx.x * 4 + (wid & 3);
                    d_s11p[(size_t)slot * BATCH + prow0 + rr] = dsum;
                }
                continue;
            }

            #pragma unroll
            for (int nt = 0; nt < 4; nt++) {
                int cn = bn + wn + (nt << 3) + ((lane & 3) << 1);
                float v0 = acc[mt][nt][half * 2 + 0];
                float v1 = acc[mt][nt][half * 2 + 1];
                if (EPI & 1) {
                    if (cn < N)     v0 += bias[cn];
                    if (cn + 1 < N) v1 += bias[cn + 1];
                }
                if (EPI & 2) { v0 = fmaxf(v0, 0.f); v1 = fmaxf(v1, 0.f); }
                if (EPI & 4) {
                    if (cn < N)     Cf[(size_t)rr * ldc + cn] = v0;
                    if (cn + 1 < N) Cf[(size_t)rr * ldc + cn + 1] = v1;
                }
                if (EPI & 8) {
                    if (cn + 1 < N) {
                        if (EPI & 16) {
                            f16 h0, l0, h1, l1;
                            split1(v0, h0, l0);
                            split1(v1, h1, l1);
                            uint32_t hp = (uint32_t)__half_as_ushort(h0) | ((uint32_t)__half_as_ushort(h1) << 16);
                            uint32_t lp = (uint32_t)__half_as_ushort(l0) | ((uint32_t)__half_as_ushort(l1) << 16);
                            *(uint32_t*)(Ch + (size_t)rr * ldc + cn) = hp;
                            *(uint32_t*)(Cl + (size_t)rr * ldc + cn) = lp;
                        } else {
                            f16 h0 = __float2half_rn(v0);
                            f16 h1 = __float2half_rn(v1);
                            uint32_t hp = (uint32_t)__half_as_ushort(h0) | ((uint32_t)__half_as_ushort(h1) << 16);
                            *(uint32_t*)(Ch + (size_t)rr * ldc + cn) = hp;
                        }
                    } else if (cn < N) {
                        f16 h0, l0;
                        split1(v0, h0, l0);
                        Ch[(size_t)rr * ldc + cn] = h0;
                        if (EPI & 16) Cl[(size_t)rr * ldc + cn] = l0;
                    }
                }
            }
        }
    }
}

// ================= small kernels =================
__device__ __forceinline__ float warpReduceSum(float v) {
    #pragma unroll
    for (int o = 16; o > 0; o >>= 1) v += __shfl_down_sync(0xffffffffu, v, o);
    return v;
}
__device__ __forceinline__ float blockReduceSum(float v, float* smem) {
    __syncthreads();
    int lane = threadIdx.x & 31, wid = threadIdx.x >> 5;
    v = warpReduceSum(v);
    if (lane == 0) smem[wid] = v;
    __syncthreads();
    int nw = blockDim.x >> 5;
    float t = (threadIdx.x < nw) ? smem[threadIdx.x] : 0.0f;
    if (wid == 0) { t = warpReduceSum(t); if (lane == 0) smem[0] = t; }
    __syncthreads();
    return smem[0];
}

__device__ __forceinline__ void pack4(float4 v, uint2& hp, uint2& lp) {
    f16 h0, l0, h1, l1, h2, l2, h3, l3;
    split1(v.x, h0, l0); split1(v.y, h1, l1);
    split1(v.z, h2, l2); split1(v.w, h3, l3);
    hp = make_uint2(
        (uint32_t)__half_as_ushort(h0) | ((uint32_t)__half_as_ushort(h1) << 16),
        (uint32_t)__half_as_ushort(h2) | ((uint32_t)__half_as_ushort(h3) << 16));
    lp = make_uint2(
        (uint32_t)__half_as_ushort(l0) | ((uint32_t)__half_as_ushort(l1) << 16),
        (uint32_t)__half_as_ushort(l2) | ((uint32_t)__half_as_ushort(l3) << 16));
}

__global__ __launch_bounds__(256) void feat_prep_kernel(const float* __restrict__ feat) {
    int b = blockIdx.x, tid = threadIdx.x;
    const float4* row = (const float4*)(feat + (size_t)b * DIM);
    float4 v0 = row[tid];
    float4 v1 = row[tid + 256];
    float s = v0.x * v0.x + v0.y * v0.y + v0.z * v0.z + v0.w * v0.w
            + v1.x * v1.x + v1.y * v1.y + v1.z * v1.z + v1.w * v1.w;
    __shared__ float red[32];
    s = blockReduceSum(s, red);
    if (tid == 0) d_rinv[b] = 1.0f / fmaxf(sqrtf(s), 1e-12f);
    uint2 hp, lp;
    size_t o = (size_t)b * DIM;
    pack4(v0, hp, lp);
    *(uint2*)(feat_h + o + tid * 4) = hp;
    *(uint2*)(feat_l + o + tid * 4) = lp;
    pack4(v1, hp, lp);
    *(uint2*)(feat_h + o + (tid + 256) * 4) = hp;
    *(uint2*)(feat_l + o + (tid + 256) * 4) = lp;
}

__global__ __launch_bounds__(256) void transpose_bf_kernel(
    const float* __restrict__ in, f16* __restrict__ oh, f16* __restrict__ ol)
{
    __shared__ float t[32][33];
    int bx = blockIdx.x * 32, by = blockIdx.y * 32;
    #pragma unroll
    for (int j = threadIdx.y; j < 32; j += 8)
        t[j][threadIdx.x] = in[(size_t)(by + j) * DIM + bx + threadIdx.x];
    __syncthreads();
    #pragma unroll
    for (int j = threadIdx.y; j < 32; j += 8) {
        float v = t[threadIdx.x][j];
        f16 h, l;
        split1(v, h, l);
        size_t o = (size_t)(bx + j) * DIM + by + threadIdx.x;
        oh[o] = h;
        if (ol) ol[o] = l;
    }
}

__global__ __launch_bounds__(256) void split_pad_kernel(
    const float* __restrict__ src, f16* __restrict__ dh, f16* __restrict__ dl,
    int valid, int total)
{
    int i = (blockIdx.x * 256 + threadIdx.x) * 4;
    if (i >= total) return;
    float4 v;
    if (i + 3 < valid) v = *(const float4*)(src + i);
    else {
        v.x = (i + 0 < valid) ? src[i + 0] : 0.f;
        v.y = (i + 1 < valid) ? src[i + 1] : 0.f;
        v.z = (i + 2 < valid) ? src[i + 2] : 0.f;
        v.w = (i + 3 < valid) ? src[i + 3] : 0.f;
    }
    uint2 hp, lp;
    pack4(v, hp, lp);
    *(uint2*)(dh + i) = hp;
    if (dl) *(uint2*)(dl + i) = lp;
}

__global__ __launch_bounds__(256) void embed_norm_kernel(const float* __restrict__ emb) {
    int n = blockIdx.x, tid = threadIdx.x;
    if (n >= NEMB) {
        f16 z = __float2half_rn(0.f);
        for (int j = tid; j < DIM; j += 256) wn_h[(size_t)n * DIM + j] = z;
        return;
    }
    const float* row = emb + (size_t)n * DIM;
    float s = 0.0f;
    for (int j = tid; j < DIM; j += 256) { float v = row[j]; s = fmaf(v, v, s); }
    __shared__ float red[32];
    s = blockReduceSum(s, red);
    float inv = 1.0f / fmaxf(sqrtf(s), 1e-12f);
    float c = 0.0f;
    for (int j = tid; j < DIM; j += 256) {
        float v = row[j] * inv;
        d_wn[(size_t)n * DIM + j] = v;
        wn_h[(size_t)n * DIM + j] = __float2half_rn(v);
        c = fmaf(v, v, c);
    }
    c = blockReduceSum(c, red);
    if (tid == 0) d_c[n] = c;
}

__global__ __launch_bounds__(256) void argmin_combine_kernel() {
    int b = blockIdx.x * 256 + threadIdx.x;
    float m = INFINITY, s = INFINITY;
    int i = 0x7fffffff;
    #pragma unroll 4
    for (int p = 0; p < 32; p++) {
        float pm = d_pmin[(size_t)p * BATCH + b];
        float ps = d_psec[(size_t)p * BATCH + b];
        int   pi = d_pidx[(size_t)p * BATCH + b];
        float nm = fminf(m, pm);
        float ns = fminf(fmaxf(m, pm), fminf(s, ps));
        int ni = (pm < m) ? pi : ((m < pm) ? i : min(i, pi));
        m = nm; s = ns; i = ni;
    }
    d_bidx[b] = i;
    d_gap[b] = s - m;
}

__global__ __launch_bounds__(256) void refine_gather_kernel(
    const float* __restrict__ emb, const float* __restrict__ feat,
    float* __restrict__ outq, float* __restrict__ outi, int row0)
{
    int b = row0 + blockIdx.x;
    int tid = threadIdx.x;
    int idx = d_bidx[b];
    if (d_gap[b] < 1e-3f) {
        __shared__ float sf[DIM];
        const float* f = feat + (size_t)b * DIM;
        for (int j = tid; j < DIM; j += 256) sf[j] = f[j];
        __syncthreads();
        float r = d_rinv[b];
        int wid = tid >> 5, lane = tid & 31;
        float best = INFINITY; int bi = 0x7fffffff;
        for (int n = wid; n < NEMB; n += 8) {
            const float* w = d_wn + (size_t)n * DIM;
            float s = 0.0f;
            for (int j = lane; j < DIM; j += 32) s = fmaf(sf[j], w[j], s);
            s = warpReduceSum(s);
            s = __shfl_sync(0xffffffffu, s, 0);
            float v = d_c[n] - 2.0f * r * s;
            if (v < best) { best = v; bi = n; }
        }
        __shared__ float wb[8]; __shared__ int wi[8];
        if (lane == 0) { wb[wid] = best; wi[wid] = bi; }
        __syncthreads();
        if (tid == 0) {
            float bb = wb[0]; int ii = wi[0];
            for (int w = 1; w < 8; w++)
                if (wb[w] < bb || (wb[w] == bb && wi[w] < ii)) { bb = wb[w]; ii = wi[w]; }
            wi[0] = ii;
        }
        __syncthreads();
        idx = wi[0];
        if (tid == 0) d_bidx[b] = idx;
    }
    const float* src = emb + (size_t)idx * DIM;
    float* dst = outq + (size_t)b * DIM;
    for (int j = tid; j < DIM; j += 256) dst[j] = src[j];
    if (tid == 0) outi[b] = (float)idx;
}

__global__ __launch_bounds__(256) void diag_kernel(const float* __restrict__ emb) {
    int n = blockIdx.x, tid = threadIdx.x;
    const float* y = d_Y + (size_t)n * DIM;
    const float* e = emb + (size_t)n * DIM;
    float s = 0.0f;
    for (int j = tid; j < DIM; j += 256) s = fmaf(y[j], e[j], s);
    __shared__ float red[32];
    s = blockReduceSum(s, red);
    if (tid == 0) d_diag[n] = s;
}

__global__ __launch_bounds__(256) void attn_mix2_kernel(
    const float* __restrict__ feat, const float* __restrict__ outq, int row0)
{
    int b = row0 + blockIdx.x;
    int tid = threadIdx.x;
    int idx = d_bidx[b];
    const float* t1 = feat + (size_t)b * DIM;
    const float* t0 = outq + (size_t)b * DIM;
    const float* yr = d_Y + (size_t)idx * DIM;
    const float* zr = d_Z + (size_t)idx * DIM;
    float s01 = 0, s10 = 0, s11 = 0;
    for (int j = tid; j < DIM; j += 256) {
        float f = t1[j];
        s01 = fmaf(yr[j], f, s01);
        s10 = fmaf(zr[j], f, s10);
    }
    if (tid < 64) s11 = d_s11p[(size_t)tid * BATCH + b];
    __shared__ float red[32];
    s01 = blockReduceSum(s01, red);
    s10 = blockReduceSum(s10, red);
    s11 = blockReduceSum(s11, red);
    float s00 = d_diag[idx];
    float m0 = fmaxf(s00, s10);
    float e00 = expf(s00 - m0), e10 = expf(s10 - m0);
    float iv0 = 1.0f / (e00 + e10);
    float a00 = e00 * iv0, a10 = e10 * iv0;
    float m1 = fmaxf(s01, s11);
    float e01 = expf(s01 - m1), e11 = expf(s11 - m1);
    float iv1 = 1.0f / (e01 + e11);
    float a01 = e01 * iv1, a11 = e11 * iv1;
    size_t go = (size_t)b * 2 * DIM;
    for (int j = tid; j < DIM; j += 256) {
        float v0 = t0[j], v1 = t1[j];
        g_h[go + j]       = __float2half_rn(fmaf(a00, v0, a10 * v1));
        g_h[go + DIM + j] = __float2half_rn(fmaf(a01, v0, a11 * v1));
    }
}

// ================= launch =================
extern "C" void kernel_launch(void* const* d_in, const int* in_sizes, int n_in,
                              void* d_out, int out_size)
{
    const float* feat = (const float*)d_in[0];
    const float* emb  = (const float*)d_in[1];
    const float* Kw   = (const float*)d_in[2];
    const float* Qw   = (const float*)d_in[3];
    const float* Vw   = (const float*)d_in[4];
    const float* fw   = (const float*)d_in[5];
    const float* fb   = (const float*)d_in[6];
    const float* fcw  = (const float*)d_in[7];
    const float* fcb  = (const float*)d_in[8];

    float* out  = (float*)d_out;
    float* outq = out;
    float* outp = out + (size_t)BATCH * DIM;
    float* outi = outp + (size_t)BATCH * NCLS;

    float *Mm, *Y, *Z;
    f16 *p_feath, *p_featl, *p_embh, *p_embl, *p_wnh;
    f16 *p_kwth, *p_kwtl, *p_qwth, *p_qwtl, *p_vwth;
    f16 *p_mh, *p_ml, *p_mth, *p_mtl, *p_fwh, *p_fcwh;
    f16 *p_pth, *p_gh, *p_hh;
    cudaGetSymbolAddress((void**)&Mm,  d_M);
    cudaGetSymbolAddress((void**)&Y,   d_Y);
    cudaGetSymbolAddress((void**)&Z,   d_Z);
    cudaGetSymbolAddress((void**)&p_feath, feat_h); cudaGetSymbolAddress((void**)&p_featl, feat_l);
    cudaGetSymbolAddress((void**)&p_embh,  emb_h);  cudaGetSymbolAddress((void**)&p_embl,  emb_l);
    cudaGetSymbolAddress((void**)&p_wnh,   wn_h);
    cudaGetSymbolAddress((void**)&p_kwth,  kwt_h);  cudaGetSymbolAddress((void**)&p_kwtl,  kwt_l);
    cudaGetSymbolAddress((void**)&p_qwth,  qwt_h);  cudaGetSymbolAddress((void**)&p_qwtl,  qwt_l);
    cudaGetSymbolAddress((void**)&p_vwth,  vwt_h);
    cudaGetSymbolAddress((void**)&p_mh,    m_h);    cudaGetSymbolAddress((void**)&p_ml,    m_l);
    cudaGetSymbolAddress((void**)&p_mth,   mt_h);   cudaGetSymbolAddress((void**)&p_mtl,   mt_l);
    cudaGetSymbolAddress((void**)&p_fwh,   fw_h);
    cudaGetSymbolAddress((void**)&p_fcwh,  fcw_h);
    cudaGetSymbolAddress((void**)&p_pth,   pt_h);
    cudaGetSymbolAddress((void**)&p_gh,    g_h);
    cudaGetSymbolAddress((void**)&p_hh,    h_h);

    cudaFuncSetAttribute((const void*)tc_gemm<64, 1>, cudaFuncAttributeMaxDynamicSharedMemorySize, SMEM_BYTES);
    cudaFuncSetAttribute((const void*)tc_gemm<28, 3>, cudaFuncAttributeMaxDynamicSharedMemorySize, SMEM_BYTES);
    cudaFuncSetAttribute((const void*)tc_gemm<4, 3>,  cudaFuncAttributeMaxDynamicSharedMemorySize, SMEM_BYTES);
    cudaFuncSetAttribute((const void*)tc_gemm<32, 3>, cudaFuncAttributeMaxDynamicSharedMemorySize, SMEM_BYTES);
    cudaFuncSetAttribute((const void*)tc_gemm<8, 1>,  cudaFuncAttributeMaxDynamicSharedMemorySize, SMEM_BYTES);
    cudaFuncSetAttribute((const void*)tc_gemm<11, 1>, cudaFuncAttributeMaxDynamicSharedMemorySize, SMEM_BYTES);
    cudaFuncSetAttribute((const void*)tc_gemm<5, 1>,  cudaFuncAttributeMaxDynamicSharedMemorySize, SMEM_BYTES);

    cudaStream_t s1 = g_ctx.s1, s2 = g_ctx.s2, s3 = g_ctx.s3;
    dim3 tb(32, 8);
    dim3 tg(DIM / 32, DIM / 32);

    // ---- fork immediately so side streams start at t=0 ----
    cudaEventRecord(g_ctx.eFork, 0);

    // ---- s1: Kw/Qw transposes, emb split -> M -> MT -> Y -> diag ----
    cudaStreamWaitEvent(s1, g_ctx.eFork, 0);
    transpose_bf_kernel<<<tg, tb, 0, s1>>>(Kw, p_kwth, p_kwtl);
    transpose_bf_kernel<<<tg, tb, 0, s1>>>(Qw, p_qwth, p_qwtl);
    split_pad_kernel<<<(NPAD * DIM / 4 + 255) / 256, 256, 0, s1>>>(emb, p_embh, p_embl, NEMB * DIM, NPAD * DIM);
    tc_gemm<28, 3><<<dim3(DIM / BN, DIM / BM), 256, SMEM_BYTES, s1>>>(
        p_kwth, p_kwtl, p_qwth, p_qwtl, nullptr, nullptr, Mm, p_mh, p_ml,
        DIM, DIM, DIM, DIM, DIM, DIM, 0);
    cudaEventRecord(g_ctx.eM, s1);
    transpose_bf_kernel<<<tg, tb, 0, s1>>>(Mm, p_mth, p_mtl);
    tc_gemm<4, 3><<<dim3(DIM / BN, NPAD / BM), 256, SMEM_BYTES, s1>>>(
        p_embh, p_embl, p_mth, p_mtl, nullptr, nullptr, Y, nullptr, nullptr,
        NEMB, DIM, DIM, DIM, DIM, DIM, 0);
    diag_kernel<<<NEMB, 256, 0, s1>>>(emb);
    cudaEventRecord(g_ctx.e1, s1);

    // ---- s2: Vw/fw/fcw prep -> Z -> PT ----
    cudaStreamWaitEvent(s2, g_ctx.eFork, 0);
    transpose_bf_kernel<<<tg, tb, 0, s2>>>(Vw, p_vwth, nullptr);
    split_pad_kernel<<<(DIM * 2 * DIM / 4 + 255) / 256, 256, 0, s2>>>(fw, p_fwh, nullptr, DIM * 2 * DIM, DIM * 2 * DIM);
    split_pad_kernel<<<(NPAD * DIM / 4 + 255) / 256, 256, 0, s2>>>(fcw, p_fcwh, nullptr, NCLS * DIM, NPAD * DIM);
    cudaStreamWaitEvent(s2, g_ctx.eM, 0);
    tc_gemm<4, 3><<<dim3(DIM / BN, NPAD / BM), 256, SMEM_BYTES, s2>>>(
        p_embh, p_embl, p_mh, p_ml, nullptr, nullptr, Z, nullptr, nullptr,
        NEMB, DIM, DIM, DIM, DIM, DIM, 0);
    tc_gemm<8, 1><<<dim3(DIM / BN, DIM / BM), 256, SMEM_BYTES, s2>>>(
        p_fwh,       nullptr, p_vwth, nullptr, nullptr, nullptr, nullptr, p_pth,       nullptr,
        DIM, DIM, DIM, 2 * DIM, DIM, 2 * DIM, 0);
    tc_gemm<8, 1><<<dim3(DIM / BN, DIM / BM), 256, SMEM_BYTES, s2>>>(
        p_fwh + DIM, nullptr, p_vwth, nullptr, nullptr, nullptr, nullptr, p_pth + DIM, nullptr,
        DIM, DIM, DIM, 2 * DIM, DIM, 2 * DIM, 0);
    cudaEventRecord(g_ctx.e2, s2);

    // ---- default: feat prep -> embed norm -> S (fused argmin) -> combine ----
    feat_prep_kernel<<<BATCH, 256>>>(feat);
    embed_norm_kernel<<<NPAD, 256>>>(emb);
    tc_gemm<64, 1><<<dim3(NPAD / BN, BATCH / BM), 256, SMEM_BYTES>>>(
        p_feath, nullptr, p_wnh, nullptr, nullptr, nullptr, nullptr, nullptr, nullptr,
        BATCH, NEMB, DIM, DIM, DIM, NEMB, 0);
    argmin_combine_kernel<<<BATCH / 256, 256>>>();
    cudaEventRecord(g_ctx.eCmb, 0);

    // ---- tail chain A (default): rows [0, 4096) ----
    refine_gather_kernel<<<HALFB, 256>>>(emb, feat, outq, outi, 0);
    cudaStreamWaitEvent(0, g_ctx.eM, 0);
    tc_gemm<32, 3><<<dim3(DIM / BN, HALFB / BM), 256, SMEM_BYTES>>>(
        p_feath, p_featl, p_mh, p_ml, nullptr, feat, nullptr, nullptr, nullptr,
        HALFB, DIM, DIM, DIM, DIM, DIM, 0);
    cudaStreamWaitEvent(0, g_ctx.e1, 0);
    cudaStreamWaitEvent(0, g_ctx.e2, 0);
    attn_mix2_kernel<<<HALFB, 256>>>(feat, outq, 0);
    tc_gemm<11, 1><<<dim3(DIM / BN, HALFB / BM), 256, SMEM_BYTES>>>(
        p_gh, nullptr, p_pth, nullptr, fb, nullptr, nullptr, p_hh, nullptr,
        HALFB, DIM, 2 * DIM, 2 * DIM, 2 * DIM, DIM, 0);
    tc_gemm<5, 1><<<dim3(NPAD / BN, HALFB / BM), 256, SMEM_BYTES>>>(
        p_hh, nullptr, p_fcwh, nullptr, fcb, nullptr, outp, nullptr, nullptr,
        HALFB, NCLS, DIM, DIM, DIM, NCLS, 0);

    // ---- tail chain B (s3): rows [4096, 8192) ----
    cudaStreamWaitEvent(s3, g_ctx.eCmb, 0);
    refine_gather_kernel<<<HALFB, 256, 0, s3>>>(emb, feat, outq, outi, HALFB);
    cudaStreamWaitEvent(s3, g_ctx.eM, 0);
    tc_gemm<32, 3><<<dim3(DIM / BN, HALFB / BM), 256, SMEM_BYTES, s3>>>(
        p_feath + (size_t)HALFB * DIM, p_featl + (size_t)HALFB * DIM, p_mh, p_ml,
        nullptr, feat + (size_t)HALFB * DIM, nullptr, nullptr, nullptr,
        HALFB, DIM, DIM, DIM, DIM, DIM, HALFB);
    cudaStreamWaitEvent(s3, g_ctx.e1, 0);
    cudaStreamWaitEvent(s3, g_ctx.e2, 0);
    attn_mix2_kernel<<<HALFB, 256, 0, s3>>>(feat, outq, HALFB);
    tc_gemm<11, 1><<<dim3(DIM / BN, HALFB / BM), 256, SMEM_BYTES, s3>>>(
        p_gh + (size_t)HALFB * 2 * DIM, nullptr, p_pth, nullptr, fb, nullptr,
        nullptr, p_hh + (size_t)HALFB * DIM, nullptr,
        HALFB, DIM, 2 * DIM, 2 * DIM, 2 * DIM, DIM, 0);
    tc_gemm<5, 1><<<dim3(NPAD / BN, HALFB / BM), 256, SMEM_BYTES, s3>>>(
        p_hh + (size_t)HALFB * DIM, nullptr, p_fcwh, nullptr, fcb, nullptr,
        outp + (size_t)HALFB * NCLS, nullptr, nullptr,
        HALFB, NCLS, DIM, DIM, DIM, NCLS, 0);
    cudaEventRecord(g_ctx.e3, s3);

    // ---- join ----
    cudaStreamWaitEvent(0, g_ctx.e3, 0);
}

// round 13
// speedup vs baseline: 1.4677x; 1.0058x over previous
#include <cuda_runtime.h>
#include <cuda_fp16.h>
#include <math.h>
#include <stdint.h>

#define BATCH 8192
#define HALFB 4096
#define DIM   2048
#define NEMB  1000
#define NCLS  1000
#define NPAD  1024

typedef __half f16;

// ---------------- fp32 scratch ----------------
__device__ float d_wn[NEMB * DIM];
__device__ float d_c[NEMB];
__device__ float d_rinv[BATCH];
__device__ float d_M[DIM * DIM];
__device__ float d_Y[NEMB * DIM];
__device__ float d_Z[NEMB * DIM];
__device__ float d_diag[NEMB];
__device__ int   d_bidx[BATCH];
__device__ float d_gap[BATCH];
__device__ float d_pmin[32 * BATCH];
__device__ float d_psec[32 * BATCH];
__device__ int   d_pidx[32 * BATCH];
__device__ float d_s11p[64 * BATCH];

// ---------------- fp16 hi/lo planes ----------------
__device__ f16 feat_h[BATCH * DIM],  feat_l[BATCH * DIM];
__device__ f16 emb_h[NPAD * DIM],    emb_l[NPAD * DIM];
__device__ f16 wn_h[NPAD * DIM];
__device__ f16 kwt_h[DIM * DIM],     kwt_l[DIM * DIM];
__device__ f16 qwt_h[DIM * DIM],     qwt_l[DIM * DIM];
__device__ f16 vwt_h[DIM * DIM];
__device__ f16 m_h[DIM * DIM],       m_l[DIM * DIM];
__device__ f16 mt_h[DIM * DIM],      mt_l[DIM * DIM];
__device__ f16 fw_h[DIM * 2 * DIM];
__device__ f16 fcw_h[NPAD * DIM];
__device__ f16 pt_h[DIM * 2 * DIM];
__device__ f16 g_h[BATCH * 2 * DIM];
__device__ f16 h_h[BATCH * DIM];

// ---------------- streams/events ----------------
namespace {
struct Ctx {
    cudaStream_t s1, s2, s3;
    cudaEvent_t eFork, eM, e1, e2, eCmb, e3;
    Ctx() {
        cudaStreamCreateWithFlags(&s1, cudaStreamNonBlocking);
        cudaStreamCreateWithFlags(&s2, cudaStreamNonBlocking);
        cudaStreamCreateWithFlags(&s3, cudaStreamNonBlocking);
        cudaEventCreateWithFlags(&eFork, cudaEventDisableTiming);
        cudaEventCreateWithFlags(&eM,    cudaEventDisableTiming);
        cudaEventCreateWithFlags(&e1,    cudaEventDisableTiming);
        cudaEventCreateWithFlags(&e2,    cudaEventDisableTiming);
        cudaEventCreateWithFlags(&eCmb,  cudaEventDisableTiming);
        cudaEventCreateWithFlags(&e3,    cudaEventDisableTiming);
    }
};
Ctx g_ctx;
}

// ---------------- helpers ----------------
__device__ __forceinline__ uint32_t smem_to_u32(const void* p) {
    uint32_t a;
    asm("{ .reg .u64 t; cvta.to.shared.u64 t, %1; cvt.u32.u64 %0, t; }" : "=r"(a) : "l"(p));
    return a;
}
__device__ __forceinline__ void split1(float v, f16& h, f16& l) {
    h = __float2half_rn(v);
    l = __float2half_rn(v - __half2float(h));
}
__device__ __forceinline__ void ldsm4(uint32_t* r, uint32_t addr) {
    asm volatile("ldmatrix.sync.aligned.m8n8.x4.shared.b16 {%0,%1,%2,%3}, [%4];"
        : "=r"(r[0]), "=r"(r[1]), "=r"(r[2]), "=r"(r[3]) : "r"(addr));
}
__device__ __forceinline__ void ldsm2(uint32_t* r, uint32_t addr) {
    asm volatile("ldmatrix.sync.aligned.m8n8.x2.shared.b16 {%0,%1}, [%2];"
        : "=r"(r[0]), "=r"(r[1]) : "r"(addr));
}
__device__ __forceinline__ void mma16816(float* d, const uint32_t* a, const uint32_t* b) {
    asm volatile("mma.sync.aligned.m16n8k16.row.col.f32.f16.f16.f32 "
        "{%0,%1,%2,%3},{%4,%5,%6,%7},{%8,%9},{%0,%1,%2,%3};"
        : "+f"(d[0]), "+f"(d[1]), "+f"(d[2]), "+f"(d[3])
        : "r"(a[0]), "r"(a[1]), "r"(a[2]), "r"(a[3]), "r"(b[0]), "r"(b[1]));
}
__device__ __forceinline__ void cpa16(uint32_t dst, const void* src) {
    asm volatile("cp.async.cg.shared.global [%0], [%1], 16;" :: "r"(dst), "l"(src));
}
#define CP_COMMIT() asm volatile("cp.async.commit_group;" ::: "memory")
#define CP_WAIT(n)  asm volatile("cp.async.wait_group %0;" :: "n"(n) : "memory")

// ================= tensor-core GEMM (pre-split fp16, NT, f32 acc, 3-stage) =================
// NPROD=1: Ah*Bh. NPROD=2: + Ah*Bl. NPROD=3: + Al*Bh.
// EPI bits: 1=bias, 2=relu, 4=write f32, 8=write f16 hi plane, 16=also write lo plane,
//           32=fused row-dot with aux -> d_s11p, 64=fused argmin -> partials
#define BM 128
#define BN 128
#define STAGE_BYTES 32768
#define SMEM_BYTES  (3 * STAGE_BYTES)

template<int EPI, int NPROD>
__global__ __launch_bounds__(256, 2)
void tc_gemm(const f16* __restrict__ Ah, const f16* __restrict__ Al,
             const f16* __restrict__ Bh, const f16* __restrict__ Bl,
             const float* __restrict__ bias, const float* __restrict__ aux,
             float* __restrict__ Cf, f16* __restrict__ Ch, f16* __restrict__ Cl,
             int M, int N, int K, int lda, int ldb, int ldc, int prow0)
{
    extern __shared__ char smem[];
    const int tid  = threadIdx.x;
    const int lane = tid & 31;
    const int wid  = tid >> 5;
    const int wm   = (wid >> 2) << 6;
    const int wn   = (wid & 3) << 5;
    const int bm   = blockIdx.y * BM;
    const int bn   = blockIdx.x * BN;
    const uint32_t sb = smem_to_u32(smem);

    float acc[4][4][4];
    #pragma unroll
    for (int i = 0; i < 4; i++)
        #pragma unroll
        for (int j = 0; j < 4; j++)
            #pragma unroll
            for (int k = 0; k < 4; k++) acc[i][j][k] = 0.f;

    auto copy = [&](int s, int k0) {
        uint32_t base = sb + s * STAGE_BYTES;
        #pragma unroll
        for (int i = 0; i < 4; i++) {
            int id = (i << 8) + tid;
            int row = id >> 3, rem = id & 7, pl = rem >> 2, u = rem & 3;
            if (NPROD == 3 || pl == 0) {
                const f16* src = (pl ? Al : Ah) + (size_t)(bm + row) * lda + k0 + (u << 3);
                uint32_t dst = base + row * 128 + ((((u ^ (row & 7))) ^ (pl << 2)) << 4);
                cpa16(dst, src);
            }
        }
        #pragma unroll
        for (int i = 0; i < 4; i++) {
            int id = (i << 8) + tid;
            int row = id >> 3, rem = id & 7, pl = rem >> 2, u = rem & 3;
            if (NPROD >= 2 || pl == 0) {
                const f16* src = (pl ? Bl : Bh) + (size_t)(bn + row) * ldb + k0 + (u << 3);
                uint32_t dst = base + 16384 + row * 128 + ((((u ^ (row & 7))) ^ (pl << 2)) << 4);
                cpa16(dst, src);
            }
        }
    };

    // 2-deep prefetch (K >= 1024 always, so nc >= 32)
    copy(0, 0);
    CP_COMMIT();
    copy(1, 32);
    CP_COMMIT();

    const int nc = K >> 5;
    int s = 0;
    for (int c = 0; c < nc; c++) {
        // guarantee stage s (group c) has landed: groups 0..c+1 committed so far
        if (c + 1 < nc) { CP_WAIT(1); } else { CP_WAIT(0); }
        __syncthreads();
        // all warps are past compute(c-1); safe to overwrite stage (c+2)%3 == (c-1)%3
        if (c + 2 < nc) {
            int s2 = s + 2; if (s2 >= 3) s2 -= 3;
            copy(s2, (c + 2) << 5);
            CP_COMMIT();
        }

        uint32_t a_s = sb + s * STAGE_BYTES;
        uint32_t b_s = a_s + 16384;
        #pragma unroll
        for (int h = 0; h < 2; h++) {
            uint32_t bhf[4][2], blf[4][2];
            #pragma unroll
            for (int nt = 0; nt < 4; nt++) {
                int r = wn + (nt << 3) + (lane & 7);
                int lu = (h << 1) + ((lane >> 3) & 1);
                uint32_t ad = b_s + r * 128 + ((uint32_t)(lu ^ (r & 7)) << 4);
                ldsm2(bhf[nt], ad);
                if (NPROD >= 2) ldsm2(blf[nt], ad ^ 64u);
            }
            #pragma unroll
            for (int mt = 0; mt < 4; mt++) {
                int g = lane >> 3;
                int r = wm + (mt << 4) + ((g & 1) << 3) + (lane & 7);
                int lu = (h << 1) + (g >> 1);
                uint32_t ad = a_s + r * 128 + ((uint32_t)(lu ^ (r & 7)) << 4);
                uint32_t af[4];
                ldsm4(af, ad);                       // A hi
                #pragma unroll
                for (int nt = 0; nt < 4; nt++) mma16816(acc[mt][nt], af, bhf[nt]);
                if (NPROD >= 2) {
                    #pragma unroll
                    for (int nt = 0; nt < 4; nt++) mma16816(acc[mt][nt], af, blf[nt]);
                }
                if (NPROD == 3) {
                    ldsm4(af, ad ^ 64u);             // A lo
                    #pragma unroll
                    for (int nt = 0; nt < 4; nt++) mma16816(acc[mt][nt], af, bhf[nt]);
                }
            }
        }
        if (++s >= 3) s = 0;
    }

    // ---------------- epilogue ----------------
    #pragma unroll
    for (int mt = 0; mt < 4; mt++) {
        #pragma unroll
        for (int half = 0; half < 2; half++) {
            int rr = bm + wm + (mt << 4) + (lane >> 2) + half * 8;
            if (rr >= M) continue;

            if (EPI & 64) {
                float rv = d_rinv[prow0 + rr];
                float bmv = INFINITY, bsv = INFINITY;
                int biv = 0x7fffffff;
                #pragma unroll
                for (int nt = 0; nt < 4; nt++) {
                    #pragma unroll
                    for (int q = 0; q < 2; q++) {
                        int cn = bn + wn + (nt << 3) + ((lane & 3) << 1) + q;
                        float v = acc[mt][nt][half * 2 + q];
                        float val = (cn < N) ? (d_c[cn] - 2.0f * rv * v) : INFINITY;
                        if (val < bmv) { bsv = bmv; bmv = val; biv = cn; }
                        else if (val < bsv) bsv = val;
                    }
                }
                #pragma unroll
                for (int o = 1; o <= 2; o <<= 1) {
                    float om = __shfl_xor_sync(0xffffffffu, bmv, o);
                    float os = __shfl_xor_sync(0xffffffffu, bsv, o);
                    int   oi = __shfl_xor_sync(0xffffffffu, biv, o);
                    float nm = fminf(bmv, om);
                    float ns = fminf(fmaxf(bmv, om), fminf(bsv, os));
                    int ni = (om < bmv) ? oi : ((bmv < om) ? biv : min(biv, oi));
                    bmv = nm; bsv = ns; biv = ni;
                }
                if ((lane & 3) == 0) {
                    int slot = blockIdx.x * 4 + (wid & 3);
                    d_pmin[(size_t)slot * BATCH + prow0 + rr] = bmv;
                    d_psec[(size_t)slot * BATCH + prow0 + rr] = bsv;
                    d_pidx[(size_t)slot * BATCH + prow0 + rr] = biv;
                }
                continue;
            }

            if (EPI & 32) {
                float dsum = 0.f;
                #pragma unroll
                for (int nt = 0; nt < 4; nt++) {
                    #pragma unroll
                    for (int q = 0; q < 2; q++) {
                        int cn = bn + wn + (nt << 3) + ((lane & 3) << 1) + q;
                        dsum += acc[mt][nt][half * 2 + q] * aux[(size_t)rr * ldc + cn];
                    }
                }
                dsum += __shfl_xor_sync(0xffffffffu, dsum, 1);
                dsum += __shfl_xor_sync(0xffffffffu, dsum, 2);
                if ((lane & 3) == 0) {
                    int slot = blockIdx.x * 4 + (wid & 3);
                    d_s11p[(size_t)slot * BATCH + prow0 + rr] = dsum;
                }
                continue;
            }

            #pragma unroll
            for (int nt = 0; nt < 4; nt++) {
                int cn = bn + wn + (nt << 3) + ((lane & 3) << 1);
                float v0 = acc[mt][nt][half * 2 + 0];
                float v1 = acc[mt][nt][half * 2 + 1];
                if (EPI & 1) {
                    if (cn < N)     v0 += bias[cn];
                    if (cn + 1 < N) v1 += bias[cn + 1];
                }
                if (EPI & 2) { v0 = fmaxf(v0, 0.f); v1 = fmaxf(v1, 0.f); }
                if (EPI & 4) {
                    if (cn < N)     Cf[(size_t)rr * ldc + cn] = v0;
                    if (cn + 1 < N) Cf[(size_t)rr * ldc + cn + 1] = v1;
                }
                if (EPI & 8) {
                    if (cn + 1 < N) {
                        if (EPI & 16) {
                            f16 h0, l0, h1, l1;
                            split1(v0, h0, l0);
                            split1(v1, h1, l1);
                            uint32_t hp = (uint32_t)__half_as_ushort(h0) | ((uint32_t)__half_as_ushort(h1) << 16);
                            uint32_t lp = (uint32_t)__half_as_ushort(l0) | ((uint32_t)__half_as_ushort(l1) << 16);
                            *(uint32_t*)(Ch + (size_t)rr * ldc + cn) = hp;
                            *(uint32_t*)(Cl + (size_t)rr * ldc + cn) = lp;
                        } else {
                            f16 h0 = __float2half_rn(v0);
                            f16 h1 = __float2half_rn(v1);
                            uint32_t hp = (uint32_t)__half_as_ushort(h0) | ((uint32_t)__half_as_ushort(h1) << 16);
                            *(uint32_t*)(Ch + (size_t)rr * ldc + cn) = hp;
                        }
                    } else if (cn < N) {
                        f16 h0, l0;
                        split1(v0, h0, l0);
                        Ch[(size_t)rr * ldc + cn] = h0;
                        if (EPI & 16) Cl[(size_t)rr * ldc + cn] = l0;
                    }
                }
            }
        }
    }
}

// ================= small kernels =================
__device__ __forceinline__ float warpReduceSum(float v) {
    #pragma unroll
    for (int o = 16; o > 0; o >>= 1) v += __shfl_down_sync(0xffffffffu, v, o);
    return v;
}
__device__ __forceinline__ float blockReduceSum(float v, float* smem) {
    __syncthreads();
    int lane = threadIdx.x & 31, wid = threadIdx.x >> 5;
    v = warpReduceSum(v);
    if (lane == 0) smem[wid] = v;
    __syncthreads();
    int nw = blockDim.x >> 5;
    float t = (threadIdx.x < nw) ? smem[threadIdx.x] : 0.0f;
    if (wid == 0) { t = warpReduceSum(t); if (lane == 0) smem[0] = t; }
    __syncthreads();
    return smem[0];
}

__device__ __forceinline__ void pack4(float4 v, uint2& hp, uint2& lp) {
    f16 h0, l0, h1, l1, h2, l2, h3, l3;
    split1(v.x, h0, l0); split1(v.y, h1, l1);
    split1(v.z, h2, l2); split1(v.w, h3, l3);
    hp = make_uint2(
        (uint32_t)__half_as_ushort(h0) | ((uint32_t)__half_as_ushort(h1) << 16),
        (uint32_t)__half_as_ushort(h2) | ((uint32_t)__half_as_ushort(h3) << 16));
    lp = make_uint2(
        (uint32_t)__half_as_ushort(l0) | ((uint32_t)__half_as_ushort(l1) << 16),
        (uint32_t)__half_as_ushort(l2) | ((uint32_t)__half_as_ushort(l3) << 16));
}

__global__ __launch_bounds__(256) void feat_prep_kernel(const float* __restrict__ feat) {
    int b = blockIdx.x, tid = threadIdx.x;
    const float4* row = (const float4*)(feat + (size_t)b * DIM);
    float4 v0 = row[tid];
    float4 v1 = row[tid + 256];
    float s = v0.x * v0.x + v0.y * v0.y + v0.z * v0.z + v0.w * v0.w
            + v1.x * v1.x + v1.y * v1.y + v1.z * v1.z + v1.w * v1.w;
    __shared__ float red[32];
    s = blockReduceSum(s, red);
    if (tid == 0) d_rinv[b] = 1.0f / fmaxf(sqrtf(s), 1e-12f);
    uint2 hp, lp;
    size_t o = (size_t)b * DIM;
    pack4(v0, hp, lp);
    *(uint2*)(feat_h + o + tid * 4) = hp;
    *(uint2*)(feat_l + o + tid * 4) = lp;
    pack4(v1, hp, lp);
    *(uint2*)(feat_h + o + (tid + 256) * 4) = hp;
    *(uint2*)(feat_l + o + (tid + 256) * 4) = lp;
}

__global__ __launch_bounds__(256) void transpose_bf_kernel(
    const float* __restrict__ in, f16* __restrict__ oh, f16* __restrict__ ol)
{
    __shared__ float t[32][33];
    int bx = blockIdx.x * 32, by = blockIdx.y * 32;
    #pragma unroll
    for (int j = threadIdx.y; j < 32; j += 8)
        t[j][threadIdx.x] = in[(size_t)(by + j) * DIM + bx + threadIdx.x];
    __syncthreads();
    #pragma unroll
    for (int j = threadIdx.y; j < 32; j += 8) {
        float v = t[threadIdx.x][j];
        f16 h, l;
        split1(v, h, l);
        size_t o = (size_t)(bx + j) * DIM + by + threadIdx.x;
        oh[o] = h;
        if (ol) ol[o] = l;
    }
}

__global__ __launch_bounds__(256) void split_pad_kernel(
    const float* __restrict__ src, f16* __restrict__ dh, f16* __restrict__ dl,
    int valid, int total)
{
    int i = (blockIdx.x * 256 + threadIdx.x) * 4;
    if (i >= total) return;
    float4 v;
    if (i + 3 < valid) v = *(const float4*)(src + i);
    else {
        v.x = (i + 0 < valid) ? src[i + 0] : 0.f;
        v.y = (i + 1 < valid) ? src[i + 1] : 0.f;
        v.z = (i + 2 < valid) ? src[i + 2] : 0.f;
        v.w = (i + 3 < valid) ? src[i + 3] : 0.f;
    }
    uint2 hp, lp;
    pack4(v, hp, lp);
    *(uint2*)(dh + i) = hp;
    if (dl) *(uint2*)(dl + i) = lp;
}

__global__ __launch_bounds__(256) void embed_norm_kernel(const float* __restrict__ emb) {
    int n = blockIdx.x, tid = threadIdx.x;
    if (n >= NEMB) {
        f16 z = __float2half_rn(0.f);
        for (int j = tid; j < DIM; j += 256) wn_h[(size_t)n * DIM + j] = z;
        return;
    }
    const float* row = emb + (size_t)n * DIM;
    float s = 0.0f;
    for (int j = tid; j < DIM; j += 256) { float v = row[j]; s = fmaf(v, v, s); }
    __shared__ float red[32];
    s = blockReduceSum(s, red);
    float inv = 1.0f / fmaxf(sqrtf(s), 1e-12f);
    float c = 0.0f;
    for (int j = tid; j < DIM; j += 256) {
        float v = row[j] * inv;
        d_wn[(size_t)n * DIM + j] = v;
        wn_h[(size_t)n * DIM + j] = __float2half_rn(v);
        c = fmaf(v, v, c);
    }
    c = blockReduceSum(c, red);
    if (tid == 0) d_c[n] = c;
}

__global__ __launch_bounds__(256) void argmin_combine_kernel() {
    int b = blockIdx.x * 256 + threadIdx.x;
    float m = INFINITY, s = INFINITY;
    int i = 0x7fffffff;
    #pragma unroll 4
    for (int p = 0; p < 32; p++) {
        float pm = d_pmin[(size_t)p * BATCH + b];
        float ps = d_psec[(size_t)p * BATCH + b];
        int   pi = d_pidx[(size_t)p * BATCH + b];
        float nm = fminf(m, pm);
        float ns = fminf(fmaxf(m, pm), fminf(s, ps));
        int ni = (pm < m) ? pi : ((m < pm) ? i : min(i, pi));
        m = nm; s = ns; i = ni;
    }
    d_bidx[b] = i;
    d_gap[b] = s - m;
}

__global__ __launch_bounds__(256) void refine_gather_kernel(
    const float* __restrict__ emb, const float* __restrict__ feat,
    float* __restrict__ outq, float* __restrict__ outi, int row0)
{
    int b = row0 + blockIdx.x;
    int tid = threadIdx.x;
    int idx = d_bidx[b];
    if (d_gap[b] < 1e-3f) {
        __shared__ float sf[DIM];
        const float* f = feat + (size_t)b * DIM;
        for (int j = tid; j < DIM; j += 256) sf[j] = f[j];
        __syncthreads();
        float r = d_rinv[b];
        int wid = tid >> 5, lane = tid & 31;
        float best = INFINITY; int bi = 0x7fffffff;
        for (int n = wid; n < NEMB; n += 8) {
            const float* w = d_wn + (size_t)n * DIM;
            float s = 0.0f;
            for (int j = lane; j < DIM; j += 32) s = fmaf(sf[j], w[j], s);
            s = warpReduceSum(s);
            s = __shfl_sync(0xffffffffu, s, 0);
            float v = d_c[n] - 2.0f * r * s;
            if (v < best) { best = v; bi = n; }
        }
        __shared__ float wb[8]; __shared__ int wi[8];
        if (lane == 0) { wb[wid] = best; wi[wid] = bi; }
        __syncthreads();
        if (tid == 0) {
            float bb = wb[0]; int ii = wi[0];
            for (int w = 1; w < 8; w++)
                if (wb[w] < bb || (wb[w] == bb && wi[w] < ii)) { bb = wb[w]; ii = wi[w]; }
            wi[0] = ii;
        }
        __syncthreads();
        idx = wi[0];
        if (tid == 0) d_bidx[b] = idx;
    }
    const float* src = emb + (size_t)idx * DIM;
    float* dst = outq + (size_t)b * DIM;
    for (int j = tid; j < DIM; j += 256) dst[j] = src[j];
    if (tid == 0) outi[b] = (float)idx;
}

__global__ __launch_bounds__(256) void diag_kernel(const float* __restrict__ emb) {
    int n = blockIdx.x, tid = threadIdx.x;
    const float* y = d_Y + (size_t)n * DIM;
    const float* e = emb + (size_t)n * DIM;
    float s = 0.0f;
    for (int j = tid; j < DIM; j += 256) s = fmaf(y[j], e[j], s);
    __shared__ float red[32];
    s = blockReduceSum(s, red);
    if (tid == 0) d_diag[n] = s;
}

__global__ __launch_bounds__(256) void attn_mix2_kernel(
    const float* __restrict__ feat, const float* __restrict__ outq, int row0)
{
    int b = row0 + blockIdx.x;
    int tid = threadIdx.x;
    int idx = d_bidx[b];
    const float* t1 = feat + (size_t)b * DIM;
    const float* t0 = outq + (size_t)b * DIM;
    const float* yr = d_Y + (size_t)idx * DIM;
    const float* zr = d_Z + (size_t)idx * DIM;
    float s01 = 0, s10 = 0, s11 = 0;
    for (int j = tid; j < DIM; j += 256) {
        float f = t1[j];
        s01 = fmaf(yr[j], f, s01);
        s10 = fmaf(zr[j], f, s10);
    }
    if (tid < 64) s11 = d_s11p[(size_t)tid * BATCH + b];
    __shared__ float red[32];
    s01 = blockReduceSum(s01, red);
    s10 = blockReduceSum(s10, red);
    s11 = blockReduceSum(s11, red);
    float s00 = d_diag[idx];
    float m0 = fmaxf(s00, s10);
    float e00 = expf(s00 - m0), e10 = expf(s10 - m0);
    float iv0 = 1.0f / (e00 + e10);
    float a00 = e00 * iv0, a10 = e10 * iv0;
    float m1 = fmaxf(s01, s11);
    float e01 = expf(s01 - m1), e11 = expf(s11 - m1);
    float iv1 = 1.0f / (e01 + e11);
    float a01 = e01 * iv1, a11 = e11 * iv1;
    size_t go = (size_t)b * 2 * DIM;
    for (int j = tid; j < DIM; j += 256) {
        float v0 = t0[j], v1 = t1[j];
        g_h[go + j]       = __float2half_rn(fmaf(a00, v0, a10 * v1));
        g_h[go + DIM + j] = __float2half_rn(fmaf(a01, v0, a11 * v1));
    }
}

// ================= launch =================
extern "C" void kernel_launch(void* const* d_in, const int* in_sizes, int n_in,
                              void* d_out, int out_size)
{
    const float* feat = (const float*)d_in[0];
    const float* emb  = (const float*)d_in[1];
    const float* Kw   = (const float*)d_in[2];
    const float* Qw   = (const float*)d_in[3];
    const float* Vw   = (const float*)d_in[4];
    const float* fw   = (const float*)d_in[5];
    const float* fb   = (const float*)d_in[6];
    const float* fcw  = (const float*)d_in[7];
    const float* fcb  = (const float*)d_in[8];

    float* out  = (float*)d_out;
    float* outq = out;
    float* outp = out + (size_t)BATCH * DIM;
    float* outi = outp + (size_t)BATCH * NCLS;

    float *Mm, *Y, *Z;
    f16 *p_feath, *p_featl, *p_embh, *p_embl, *p_wnh;
    f16 *p_kwth, *p_kwtl, *p_qwth, *p_qwtl, *p_vwth;
    f16 *p_mh, *p_ml, *p_mth, *p_mtl, *p_fwh, *p_fcwh;
    f16 *p_pth, *p_gh, *p_hh;
    cudaGetSymbolAddress((void**)&Mm,  d_M);
    cudaGetSymbolAddress((void**)&Y,   d_Y);
    cudaGetSymbolAddress((void**)&Z,   d_Z);
    cudaGetSymbolAddress((void**)&p_feath, feat_h); cudaGetSymbolAddress((void**)&p_featl, feat_l);
    cudaGetSymbolAddress((void**)&p_embh,  emb_h);  cudaGetSymbolAddress((void**)&p_embl,  emb_l);
    cudaGetSymbolAddress((void**)&p_wnh,   wn_h);
    cudaGetSymbolAddress((void**)&p_kwth,  kwt_h);  cudaGetSymbolAddress((void**)&p_kwtl,  kwt_l);
    cudaGetSymbolAddress((void**)&p_qwth,  qwt_h);  cudaGetSymbolAddress((void**)&p_qwtl,  qwt_l);
    cudaGetSymbolAddress((void**)&p_vwth,  vwt_h);
    cudaGetSymbolAddress((void**)&p_mh,    m_h);    cudaGetSymbolAddress((void**)&p_ml,    m_l);
    cudaGetSymbolAddress((void**)&p_mth,   mt_h);   cudaGetSymbolAddress((void**)&p_mtl,   mt_l);
    cudaGetSymbolAddress((void**)&p_fwh,   fw_h);
    cudaGetSymbolAddress((void**)&p_fcwh,  fcw_h);
    cudaGetSymbolAddress((void**)&p_pth,   pt_h);
    cudaGetSymbolAddress((void**)&p_gh,    g_h);
    cudaGetSymbolAddress((void**)&p_hh,    h_h);

    cudaFuncSetAttribute((const void*)tc_gemm<64, 1>, cudaFuncAttributeMaxDynamicSharedMemorySize, SMEM_BYTES);
    cudaFuncSetAttribute((const void*)tc_gemm<28, 3>, cudaFuncAttributeMaxDynamicSharedMemorySize, SMEM_BYTES);
    cudaFuncSetAttribute((const void*)tc_gemm<4, 3>,  cudaFuncAttributeMaxDynamicSharedMemorySize, SMEM_BYTES);
    cudaFuncSetAttribute((const void*)tc_gemm<32, 3>, cudaFuncAttributeMaxDynamicSharedMemorySize, SMEM_BYTES);
    cudaFuncSetAttribute((const void*)tc_gemm<8, 1>,  cudaFuncAttributeMaxDynamicSharedMemorySize, SMEM_BYTES);
    cudaFuncSetAttribute((const void*)tc_gemm<11, 1>, cudaFuncAttributeMaxDynamicSharedMemorySize, SMEM_BYTES);
    cudaFuncSetAttribute((const void*)tc_gemm<5, 1>,  cudaFuncAttributeMaxDynamicSharedMemorySize, SMEM_BYTES);

    cudaStream_t s1 = g_ctx.s1, s2 = g_ctx.s2, s3 = g_ctx.s3;
    dim3 tb(32, 8);
    dim3 tg(DIM / 32, DIM / 32);

    // ---- fork immediately so side streams start at t=0 ----
    cudaEventRecord(g_ctx.eFork, 0);

    // ---- s1: Kw/Qw transposes, emb split -> M -> MT -> Y -> diag ----
    cudaStreamWaitEvent(s1, g_ctx.eFork, 0);
    transpose_bf_kernel<<<tg, tb, 0, s1>>>(Kw, p_kwth, p_kwtl);
    transpose_bf_kernel<<<tg, tb, 0, s1>>>(Qw, p_qwth, p_qwtl);
    split_pad_kernel<<<(NPAD * DIM / 4 + 255) / 256, 256, 0, s1>>>(emb, p_embh, p_embl, NEMB * DIM, NPAD * DIM);
    tc_gemm<28, 3><<<dim3(DIM / BN, DIM / BM), 256, SMEM_BYTES, s1>>>(
        p_kwth, p_kwtl, p_qwth, p_qwtl, nullptr, nullptr, Mm, p_mh, p_ml,
        DIM, DIM, DIM, DIM, DIM, DIM, 0);
    cudaEventRecord(g_ctx.eM, s1);
    transpose_bf_kernel<<<tg, tb, 0, s1>>>(Mm, p_mth, p_mtl);
    tc_gemm<4, 3><<<dim3(DIM / BN, NPAD / BM), 256, SMEM_BYTES, s1>>>(
        p_embh, p_embl, p_mth, p_mtl, nullptr, nullptr, Y, nullptr, nullptr,
        NEMB, DIM, DIM, DIM, DIM, DIM, 0);
    diag_kernel<<<NEMB, 256, 0, s1>>>(emb);
    cudaEventRecord(g_ctx.e1, s1);

    // ---- s2: Vw/fw/fcw prep -> Z -> PT ----
    cudaStreamWaitEvent(s2, g_ctx.eFork, 0);
    transpose_bf_kernel<<<tg, tb, 0, s2>>>(Vw, p_vwth, nullptr);
    split_pad_kernel<<<(DIM * 2 * DIM / 4 + 255) / 256, 256, 0, s2>>>(fw, p_fwh, nullptr, DIM * 2 * DIM, DIM * 2 * DIM);
    split_pad_kernel<<<(NPAD * DIM / 4 + 255) / 256, 256, 0, s2>>>(fcw, p_fcwh, nullptr, NCLS * DIM, NPAD * DIM);
    cudaStreamWaitEvent(s2, g_ctx.eM, 0);
    tc_gemm<4, 3><<<dim3(DIM / BN, NPAD / BM), 256, SMEM_BYTES, s2>>>(
        p_embh, p_embl, p_mh, p_ml, nullptr, nullptr, Z, nullptr, nullptr,
        NEMB, DIM, DIM, DIM, DIM, DIM, 0);
    tc_gemm<8, 1><<<dim3(DIM / BN, DIM / BM), 256, SMEM_BYTES, s2>>>(
        p_fwh,       nullptr, p_vwth, nullptr, nullptr, nullptr, nullptr, p_pth,       nullptr,
        DIM, DIM, DIM, 2 * DIM, DIM, 2 * DIM, 0);
    tc_gemm<8, 1><<<dim3(DIM / BN, DIM / BM), 256, SMEM_BYTES, s2>>>(
        p_fwh + DIM, nullptr, p_vwth, nullptr, nullptr, nullptr, nullptr, p_pth + DIM, nullptr,
        DIM, DIM, DIM, 2 * DIM, DIM, 2 * DIM, 0);
    cudaEventRecord(g_ctx.e2, s2);

    // ---- default: feat prep -> embed norm -> S (fused argmin) -> combine ----
    feat_prep_kernel<<<BATCH, 256>>>(feat);
    embed_norm_kernel<<<NPAD, 256>>>(emb);
    tc_gemm<64, 1><<<dim3(NPAD / BN, BATCH / BM), 256, SMEM_BYTES>>>(
        p_feath, nullptr, p_wnh, nullptr, nullptr, nullptr, nullptr, nullptr, nullptr,
        BATCH, NEMB, DIM, DIM, DIM, NEMB, 0);
    argmin_combine_kernel<<<BATCH / 256, 256>>>();
    cudaEventRecord(g_ctx.eCmb, 0);

    // ---- tail chain A (default): rows [0, 4096) ----
    refine_gather_kernel<<<HALFB, 256>>>(emb, feat, outq, outi, 0);
    cudaStreamWaitEvent(0, g_ctx.eM, 0);
    tc_gemm<32, 3><<<dim3(DIM / BN, HALFB / BM), 256, SMEM_BYTES>>>(
        p_feath, p_featl, p_mh, p_ml, nullptr, feat, nullptr, nullptr, nullptr,
        HALFB, DIM, DIM, DIM, DIM, DIM, 0);
    cudaStreamWaitEvent(0, g_ctx.e1, 0);
    cudaStreamWaitEvent(0, g_ctx.e2, 0);
    attn_mix2_kernel<<<HALFB, 256>>>(feat, outq, 0);
    tc_gemm<11, 1><<<dim3(DIM / BN, HALFB / BM), 256, SMEM_BYTES>>>(
        p_gh, nullptr, p_pth, nullptr, fb, nullptr, nullptr, p_hh, nullptr,
        HALFB, DIM, 2 * DIM, 2 * DIM, 2 * DIM, DIM, 0);
    tc_gemm<5, 1><<<dim3(NPAD / BN, HALFB / BM), 256, SMEM_BYTES>>>(
        p_hh, nullptr, p_fcwh, nullptr, fcb, nullptr, outp, nullptr, nullptr,
        HALFB, NCLS, DIM, DIM, DIM, NCLS, 0);

    // ---- tail chain B (s3): rows [4096, 8192) ----
    cudaStreamWaitEvent(s3, g_ctx.eCmb, 0);
    refine_gather_kernel<<<HALFB, 256, 0, s3>>>(emb, feat, outq, outi, HALFB);
    cudaStreamWaitEvent(s3, g_ctx.eM, 0);
    tc_gemm<32, 3><<<dim3(DIM / BN, HALFB / BM), 256, SMEM_BYTES, s3>>>(
        p_feath + (size_t)HALFB * DIM, p_featl + (size_t)HALFB * DIM, p_mh, p_ml,
        nullptr, feat + (size_t)HALFB * DIM, nullptr, nullptr, nullptr,
        HALFB, DIM, DIM, DIM, DIM, DIM, HALFB);
    cudaStreamWaitEvent(s3, g_ctx.e1, 0);
    cudaStreamWaitEvent(s3, g_ctx.e2, 0);
    attn_mix2_kernel<<<HALFB, 256, 0, s3>>>(feat, outq, HALFB);
    tc_gemm<11, 1><<<dim3(DIM / BN, HALFB / BM), 256, SMEM_BYTES, s3>>>(
        p_gh + (size_t)HALFB * 2 * DIM, nullptr, p_pth, nullptr, fb, nullptr,
        nullptr, p_hh + (size_t)HALFB * DIM, nullptr,
        HALFB, DIM, 2 * DIM, 2 * DIM, 2 * DIM, DIM, 0);
    tc_gemm<5, 1><<<dim3(NPAD / BN, HALFB / BM), 256, SMEM_BYTES, s3>>>(
        p_hh + (size_t)HALFB * DIM, nullptr, p_fcwh, nullptr, fcb, nullptr,
        outp + (size_t)HALFB * NCLS, nullptr, nullptr,
        HALFB, NCLS, DIM, DIM, DIM, NCLS, 0);
    cudaEventRecord(g_ctx.e3, s3);

    // ---- join ----
    cudaStreamWaitEvent(0, g_ctx.e3, 0);
}